// round 12
// baseline (speedup 1.0000x reference)
#include <cuda_runtime.h>
#include <cuda_fp16.h>
#include <math.h>
#include <stdint.h>

// Problem constants (fixed by the dataset instance)
#define NHEADS 8
#define NPOINTS 4
#define DMODEL 256
#define DHEAD 32
#define BATCH 8
#define QLEN 2048
#define HWTOT 10000
#define NPROJ 96   // 64 offset cols + 32 attn cols

// Scratch (device globals — no allocation allowed)
__device__ __half g_valh[(size_t)BATCH * HWTOT * DMODEL];    // 40.96 MB
__device__ __half g_samph[(size_t)BATCH * QLEN * DMODEL];    //  8.39 MB
__device__ float  g_proj[(size_t)BATCH * QLEN * NPROJ];
__device__ float  g_Wcat[DMODEL * NPROJ];
__device__ float  g_bcat[NPROJ];
__device__ __half g_WvalTh[DMODEL * DMODEL];                 // [N][K] half
__device__ __half g_WoutTh[DMODEL * DMODEL];
__device__ int    g_tidx[(size_t)BATCH * QLEN * NHEADS * 16];
__device__ float  g_tw[(size_t)BATCH * QLEN * NHEADS * 16];

// ---------------------------------------------------------------------------
// helpers
// ---------------------------------------------------------------------------
__device__ __forceinline__ uint32_t f2tf32(float x) {
    uint32_t u;
    asm("cvt.rna.tf32.f32 %0, %1;" : "=r"(u) : "f"(x));
    return u;
}
__device__ __forceinline__ float tf32f(float x) {
    return __uint_as_float(f2tf32(x));
}
__device__ __forceinline__ uint32_t packh2(float x, float y) {
    __half2 h = __floats2half2_rn(x, y);
    return *(uint32_t*)&h;
}

__device__ __forceinline__ void mma16816(float d[4],
                                         uint32_t a0, uint32_t a1, uint32_t a2, uint32_t a3,
                                         uint32_t b0, uint32_t b1) {
    asm volatile(
        "mma.sync.aligned.m16n8k16.row.col.f32.f16.f16.f32 "
        "{%0,%1,%2,%3}, {%4,%5,%6,%7}, {%8,%9}, {%0,%1,%2,%3};"
        : "+f"(d[0]), "+f"(d[1]), "+f"(d[2]), "+f"(d[3])
        : "r"(a0), "r"(a1), "r"(a2), "r"(a3), "r"(b0), "r"(b1));
}
__device__ __forceinline__ void mma8(float d[4],
                                     uint32_t a0, uint32_t a1, uint32_t a2, uint32_t a3,
                                     uint32_t b0, uint32_t b1) {
    asm volatile(
        "mma.sync.aligned.m16n8k8.row.col.f32.tf32.tf32.f32 "
        "{%0,%1,%2,%3}, {%4,%5,%6,%7}, {%8,%9}, {%0,%1,%2,%3};"
        : "+f"(d[0]), "+f"(d[1]), "+f"(d[2]), "+f"(d[3])
        : "r"(a0), "r"(a1), "r"(a2), "r"(a3), "r"(b0), "r"(b1));
}
__device__ __forceinline__ void cpasync16(uint32_t smem_addr, const void* gptr) {
    asm volatile("cp.async.cg.shared.global [%0], [%1], 16;\n"
                 :: "r"(smem_addr), "l"(gptr));
}
__device__ __forceinline__ void cpasync16p(uint32_t smem_addr, const void* gptr, bool valid) {
    int sz = valid ? 16 : 0;
    asm volatile("cp.async.cg.shared.global [%0], [%1], 16, %2;\n"
                 :: "r"(smem_addr), "l"(gptr), "r"(sz));
}
__device__ __forceinline__ void cpasync_commit() {
    asm volatile("cp.async.commit_group;\n" ::);
}
template<int Ncp>
__device__ __forceinline__ void cpasync_wait() {
    asm volatile("cp.async.wait_group %0;\n" :: "n"(Ncp));
}

// ---------------------------------------------------------------------------
// FP16 tensor-core GEMM, cp.async pipeline (4 stages for fp32-A, 3 for half-A).
//   AH = A half in gmem; CH = C stored as half.
// C[M,N] = A[M,K] @ BT^T + bias  (BT half [N,K] row-major).
// Block tile 128x128x32; rows multiple of 128, K%32==0.
// Single barrier per k-iteration.
// ---------------------------------------------------------------------------
#define FBM 128
#define FBN 128
#define FBK 32
#define FSTRF 36   // floats per A row (fp32 variant)
#define FSTRH 40   // halfs per row (half variant / B)

template<bool AH, bool CH>
__global__ __launch_bounds__(256) void fp16_gemm_kernel(
    const void* __restrict__ Av, const __half* __restrict__ BT,
    const float* __restrict__ bias, void* __restrict__ Cv,
    int N, int K)
{
    constexpr int FSTAGES = AH ? 3 : 4;
    extern __shared__ __align__(16) char fsm[];
    const int aStageBytes = AH ? (FBM * FSTRH * 2) : (FBM * FSTRF * 4);
    const int bStageBytes = FBN * FSTRH * 2;
    char* Abase = fsm;
    char* Bbase = fsm + FSTAGES * aStageBytes;

    const int t = threadIdx.x;
    const int warp = t >> 5;
    const int lane = t & 31;
    const int g = lane >> 2;
    const int tig = lane & 3;
    const int wm = (warp >> 1) * 32;
    const int wn = (warp & 1) * 64;

    const int rowTile = blockIdx.y * FBM;
    const int colTile = blockIdx.x * FBN;
    const __half* Bg = BT + (long)colTile * K;

    uint32_t sAaddr[4], sBaddr[2];
    const char* gA[4];
    const __half* gB[2];
    if (AH) {
        const __half* Ag = (const __half*)Av + (long)rowTile * K;
        #pragma unroll
        for (int j = 0; j < 2; j++) {
            const int idx = t + j * 256;
            const int r = idx >> 2;
            const int hc = (idx & 3) * 8;
            sAaddr[j] = (uint32_t)__cvta_generic_to_shared(Abase + (r * FSTRH + hc) * 2);
            gA[j] = (const char*)(Ag + (long)r * K + hc);
        }
    } else {
        const float* Ag = (const float*)Av + (long)rowTile * K;
        #pragma unroll
        for (int j = 0; j < 4; j++) {
            const int idx = t + j * 256;
            const int r = idx >> 3;
            const int fc = idx & 7;
            sAaddr[j] = (uint32_t)__cvta_generic_to_shared(Abase + (r * FSTRF + fc * 4) * 4);
            gA[j] = (const char*)(Ag + (long)r * K + fc * 4);
        }
    }
    #pragma unroll
    for (int j = 0; j < 2; j++) {
        const int idx = t + j * 256;
        const int r = idx >> 2;
        const int hc = (idx & 3) * 8;
        sBaddr[j] = (uint32_t)__cvta_generic_to_shared(Bbase + (r * FSTRH + hc) * 2);
        gB[j] = Bg + (long)r * K + hc;
    }

    const int kIters = K / FBK;
    auto issue_tile = [&](int tile) {
        if (tile < kIters) {
            const int s = tile % FSTAGES;
            const int k0 = tile * FBK;
            if (AH) {
                #pragma unroll
                for (int j = 0; j < 2; j++)
                    cpasync16(sAaddr[j] + s * aStageBytes, gA[j] + (long)k0 * 2);
            } else {
                #pragma unroll
                for (int j = 0; j < 4; j++)
                    cpasync16(sAaddr[j] + s * aStageBytes, gA[j] + (long)k0 * 4);
            }
            #pragma unroll
            for (int j = 0; j < 2; j++)
                cpasync16(sBaddr[j] + s * bStageBytes, gB[j] + k0);
        }
        cpasync_commit();
    };

    float acc[2][8][4];
    #pragma unroll
    for (int i = 0; i < 2; i++)
        #pragma unroll
        for (int j = 0; j < 8; j++)
            #pragma unroll
            for (int r = 0; r < 4; r++) acc[i][j][r] = 0.f;

    #pragma unroll
    for (int s = 0; s < FSTAGES - 1; s++) issue_tile(s);

    #pragma unroll 1
    for (int it = 0; it < kIters; ++it) {
        cpasync_wait<FSTAGES - 2>();
        __syncthreads();   // orders iter it-1's compute before this issue
        issue_tile(it + FSTAGES - 1);

        const int s = it % FSTAGES;
        const __half* BsS = (const __half*)(Bbase + s * bStageBytes);

        #pragma unroll
        for (int ks = 0; ks < 2; ks++) {
            const int kb = ks * 16 + 2 * tig;
            uint32_t af[2][4];
            if (AH) {
                const __half* AsS = (const __half*)(Abase + s * aStageBytes);
                #pragma unroll
                for (int mt = 0; mt < 2; mt++) {
                    const int m0 = wm + mt * 16;
                    af[mt][0] = *(const uint32_t*)&AsS[(m0 + g) * FSTRH + kb];
                    af[mt][1] = *(const uint32_t*)&AsS[(m0 + g + 8) * FSTRH + kb];
                    af[mt][2] = *(const uint32_t*)&AsS[(m0 + g) * FSTRH + kb + 8];
                    af[mt][3] = *(const uint32_t*)&AsS[(m0 + g + 8) * FSTRH + kb + 8];
                }
            } else {
                const float* AsS = (const float*)(Abase + s * aStageBytes);
                #pragma unroll
                for (int mt = 0; mt < 2; mt++) {
                    const int m0 = wm + mt * 16;
                    float2 v0 = *(const float2*)&AsS[(m0 + g) * FSTRF + kb];
                    float2 v1 = *(const float2*)&AsS[(m0 + g + 8) * FSTRF + kb];
                    float2 v2 = *(const float2*)&AsS[(m0 + g) * FSTRF + kb + 8];
                    float2 v3 = *(const float2*)&AsS[(m0 + g + 8) * FSTRF + kb + 8];
                    af[mt][0] = packh2(v0.x, v0.y);
                    af[mt][1] = packh2(v1.x, v1.y);
                    af[mt][2] = packh2(v2.x, v2.y);
                    af[mt][3] = packh2(v3.x, v3.y);
                }
            }
            uint32_t bf[8][2];
            #pragma unroll
            for (int nt = 0; nt < 8; nt++) {
                const int n0 = wn + nt * 8;
                bf[nt][0] = *(const uint32_t*)&BsS[(n0 + g) * FSTRH + kb];
                bf[nt][1] = *(const uint32_t*)&BsS[(n0 + g) * FSTRH + kb + 8];
            }
            #pragma unroll
            for (int mt = 0; mt < 2; mt++)
                #pragma unroll
                for (int nt = 0; nt < 8; nt++)
                    mma16816(acc[mt][nt], af[mt][0], af[mt][1], af[mt][2], af[mt][3],
                             bf[nt][0], bf[nt][1]);
        }
    }

    #pragma unroll
    for (int mt = 0; mt < 2; mt++) {
        #pragma unroll
        for (int nt = 0; nt < 8; nt++) {
            const int c = colTile + wn + nt * 8 + tig * 2;
            const float b0 = bias[c], b1 = bias[c + 1];
            const int r0 = rowTile + wm + mt * 16 + g;
            if (CH) {
                __half* C = (__half*)Cv;
                *(__half2*)(C + (long)r0 * N + c) =
                    __floats2half2_rn(acc[mt][nt][0] + b0, acc[mt][nt][1] + b1);
                *(__half2*)(C + (long)(r0 + 8) * N + c) =
                    __floats2half2_rn(acc[mt][nt][2] + b0, acc[mt][nt][3] + b1);
            } else {
                float* C = (float*)Cv;
                *(float2*)(C + (long)r0 * N + c) =
                    make_float2(acc[mt][nt][0] + b0, acc[mt][nt][1] + b1);
                *(float2*)(C + (long)(r0 + 8) * N + c) =
                    make_float2(acc[mt][nt][2] + b0, acc[mt][nt][3] + b1);
            }
        }
    }
}

#define FP16_SMEM_F32A (4 * (FBM * FSTRF * 4 + FBN * FSTRH * 2))   // 4-stage: 113,664
#define FP16_SMEM_H16A (3 * (FBM * FSTRH * 2 + FBN * FSTRH * 2))   // 3-stage: 61,440

// ---------------------------------------------------------------------------
// mma.sync 3xTF32 split GEMM (precision-critical offset/attn projection only).
// ---------------------------------------------------------------------------
#define GBM 128
#define GBN 128
#define GBK 16
#define STAGES 4
#define AS_STRIDE 20
#define BS_STRIDE 132
#define GEMM_SMEM_BYTES (STAGES * (GBM * AS_STRIDE + GBK * BS_STRIDE) * 4)

__global__ __launch_bounds__(256) void tf32_split_gemm_kernel(
    const float* __restrict__ A, const float* __restrict__ B,
    const float* __restrict__ bias, float* __restrict__ C,
    int M, int N, int K)
{
    extern __shared__ __align__(16) float dsmf[];
    float* As = dsmf;
    float* Bs = dsmf + STAGES * GBM * AS_STRIDE;

    const int t = threadIdx.x;
    const int warp = t >> 5;
    const int lane = t & 31;
    const int g = lane >> 2;
    const int tig = lane & 3;
    const int wm = (warp >> 1) * 32;
    const int wn = (warp & 1) * 64;

    const int rowTile = blockIdx.y * GBM;
    const int colTile = blockIdx.x * GBN;

    const int ar0 = t >> 2;
    const int ar1 = ar0 + 64;
    const int ac = (t & 3) * 4;
    const int bk0 = t >> 5;
    const int bk1 = bk0 + 8;
    const int bc = (t & 31) * 4;

    const bool aok0 = (rowTile + ar0) < M;
    const bool aok1 = (rowTile + ar1) < M;
    const bool bok = (colTile + bc) < N;

    const float* Ap0 = A + (long)(rowTile + ar0) * K + ac;
    const float* Ap1 = A + (long)(rowTile + ar1) * K + ac;
    const float* Bp0 = B + (long)bk0 * N + colTile + bc;
    const float* Bp1 = B + (long)bk1 * N + colTile + bc;

    const uint32_t aStageB = GBM * AS_STRIDE * 4;
    const uint32_t bStageB = GBK * BS_STRIDE * 4;
    const uint32_t sA0 = (uint32_t)__cvta_generic_to_shared(As + ar0 * AS_STRIDE + ac);
    const uint32_t sA1 = (uint32_t)__cvta_generic_to_shared(As + ar1 * AS_STRIDE + ac);
    const uint32_t sB0 = (uint32_t)__cvta_generic_to_shared(Bs + bk0 * BS_STRIDE + bc);
    const uint32_t sB1 = (uint32_t)__cvta_generic_to_shared(Bs + bk1 * BS_STRIDE + bc);

    const int kIters = K / GBK;

    auto issue_tile = [&](int tile) {
        if (tile < kIters) {
            const int s = tile % STAGES;
            const long k0 = (long)tile * GBK;
            cpasync16p(sA0 + s * aStageB, Ap0 + k0, aok0);
            cpasync16p(sA1 + s * aStageB, Ap1 + k0, aok1);
            cpasync16p(sB0 + s * bStageB, Bp0 + k0 * N, bok);
            cpasync16p(sB1 + s * bStageB, Bp1 + k0 * N, bok);
        }
        cpasync_commit();
    };

    float acc[2][8][4];
    #pragma unroll
    for (int i = 0; i < 2; i++)
        #pragma unroll
        for (int j = 0; j < 8; j++)
            #pragma unroll
            for (int r = 0; r < 4; r++) acc[i][j][r] = 0.f;

    #pragma unroll
    for (int s = 0; s < STAGES - 1; s++) issue_tile(s);

    #pragma unroll 1
    for (int it = 0; it < kIters; ++it) {
        cpasync_wait<STAGES - 2>();
        __syncthreads();
        issue_tile(it + STAGES - 1);

        const int s = it % STAGES;
        const float* AsS = As + s * GBM * AS_STRIDE;
        const float* BsS = Bs + s * GBK * BS_STRIDE;

        #pragma unroll
        for (int kk = 0; kk < GBK; kk += 8) {
            float ar[2][4];
            #pragma unroll
            for (int mt = 0; mt < 2; mt++) {
                const int m0 = wm + mt * 16;
                ar[mt][0] = AsS[(m0 + g) * AS_STRIDE + kk + tig];
                ar[mt][1] = AsS[(m0 + g + 8) * AS_STRIDE + kk + tig];
                ar[mt][2] = AsS[(m0 + g) * AS_STRIDE + kk + tig + 4];
                ar[mt][3] = AsS[(m0 + g + 8) * AS_STRIDE + kk + tig + 4];
            }
            float br[8][2];
            #pragma unroll
            for (int nt = 0; nt < 8; nt++) {
                br[nt][0] = BsS[(kk + tig) * BS_STRIDE + wn + nt * 8 + g];
                br[nt][1] = BsS[(kk + tig + 4) * BS_STRIDE + wn + nt * 8 + g];
            }
            uint32_t ahi[2][4], alo[2][4];
            #pragma unroll
            for (int mt = 0; mt < 2; mt++)
                #pragma unroll
                for (int r = 0; r < 4; r++) {
                    float hi = tf32f(ar[mt][r]);
                    ahi[mt][r] = __float_as_uint(hi);
                    alo[mt][r] = f2tf32(ar[mt][r] - hi);
                }
            uint32_t bhi[8][2], blo[8][2];
            #pragma unroll
            for (int nt = 0; nt < 8; nt++)
                #pragma unroll
                for (int r = 0; r < 2; r++) {
                    float hi = tf32f(br[nt][r]);
                    bhi[nt][r] = __float_as_uint(hi);
                    blo[nt][r] = f2tf32(br[nt][r] - hi);
                }
            #pragma unroll
            for (int mt = 0; mt < 2; mt++)
                #pragma unroll
                for (int nt = 0; nt < 8; nt++) {
                    mma8(acc[mt][nt], ahi[mt][0], ahi[mt][1], ahi[mt][2], ahi[mt][3],
                         blo[nt][0], blo[nt][1]);
                    mma8(acc[mt][nt], alo[mt][0], alo[mt][1], alo[mt][2], alo[mt][3],
                         bhi[nt][0], bhi[nt][1]);
                    mma8(acc[mt][nt], ahi[mt][0], ahi[mt][1], ahi[mt][2], ahi[mt][3],
                         bhi[nt][0], bhi[nt][1]);
                }
        }
        __syncthreads();
    }

    #pragma unroll
    for (int mt = 0; mt < 2; mt++) {
        #pragma unroll
        for (int nt = 0; nt < 8; nt++) {
            const int c = colTile + wn + nt * 8 + tig * 2;
            if (c >= N) continue;
            const float b0 = bias[c], b1 = bias[c + 1];
            const int r0 = rowTile + wm + mt * 16 + g;
            if (r0 < M) {
                float2 v = make_float2(acc[mt][nt][0] + b0, acc[mt][nt][1] + b1);
                *(float2*)(C + (long)r0 * N + c) = v;
            }
            const int r1 = r0 + 8;
            if (r1 < M) {
                float2 v = make_float2(acc[mt][nt][2] + b0, acc[mt][nt][3] + b1);
                *(float2*)(C + (long)r1 * N + c) = v;
            }
        }
    }
}

// ---------------------------------------------------------------------------
// Prep kernels
// ---------------------------------------------------------------------------
__global__ void prep_wcat_kernel(const float* __restrict__ W_off, const float* __restrict__ b_off,
                                 const float* __restrict__ W_attn, const float* __restrict__ b_attn)
{
    int i = blockIdx.x * blockDim.x + threadIdx.x;
    if (i < DMODEL * NPROJ) {
        int k = i / NPROJ, n = i % NPROJ;
        g_Wcat[i] = (n < 64) ? W_off[k * 64 + n] : W_attn[k * 32 + (n - 64)];
    }
    if (i < NPROJ) g_bcat[i] = (i < 64) ? b_off[i] : b_attn[i - 64];
}

// Transpose one 256x256 fp32 matrix into half [N][K].
__global__ void transpose_w_kernel(const float* __restrict__ W, __half* __restrict__ T)
{
    __shared__ float t[32][33];
    const int bi = blockIdx.x;
    const int tx = bi & 7, ty = bi >> 3;
    int x = tx * 32 + threadIdx.x;
    int y = ty * 32 + threadIdx.y;
    #pragma unroll
    for (int i = 0; i < 32; i += 8)
        t[threadIdx.y + i][threadIdx.x] = W[(y + i) * DMODEL + x];
    __syncthreads();
    x = ty * 32 + threadIdx.x;
    y = tx * 32 + threadIdx.y;
    #pragma unroll
    for (int i = 0; i < 32; i += 8)
        T[(y + i) * DMODEL + x] = __float2half_rn(t[threadIdx.x][threadIdx.y + i]);
}

// ---------------------------------------------------------------------------
// Prep table: coalesced smem staging of g_proj; thread = (bq_local, head).
// ---------------------------------------------------------------------------
__global__ __launch_bounds__(256) void prep_tab_kernel(
    const float* __restrict__ ref_pts,
    const int* __restrict__ hp, const int* __restrict__ wp)
{
    __shared__ float sproj[32 * NPROJ];
    __shared__ float sref[64];

    const int tid = threadIdx.x;
    const int bq0 = blockIdx.x * 32;

    #pragma unroll
    for (int j = 0; j < 12; j++)
        sproj[tid + j * 256] = g_proj[(long)bq0 * NPROJ + tid + j * 256];
    if (tid < 64) sref[tid] = ref_pts[(long)bq0 * 2 + tid];
    __syncthreads();

    const int bql = tid >> 3;
    const int h = tid & 7;
    const int bq = bq0 + bql;
    const int b = bq / QLEN;
    const float* pr = sproj + bql * NPROJ;

    float l0 = pr[64 + h * 4 + 0], l1 = pr[64 + h * 4 + 1];
    float l2 = pr[64 + h * 4 + 2], l3 = pr[64 + h * 4 + 3];
    float m = fmaxf(fmaxf(l0, l1), fmaxf(l2, l3));
    float e0 = expf(l0 - m), e1 = expf(l1 - m), e2 = expf(l2 - m), e3 = expf(l3 - m);
    float inv = 1.f / (e0 + e1 + e2 + e3);
    float attn[NPOINTS] = { e0 * inv, e1 * inv, e2 * inv, e3 * inv };

    const int ww = *wp;
    const int hh = *hp;
    const float rx = sref[bql * 2 + 0];
    const float ry = sref[bql * 2 + 1];
    const int vbase = b * HWTOT * DMODEL + h * DHEAD;

    const long tslot = (long)bq * NHEADS + h;
    int* ti = g_tidx + tslot * 16;
    float* tw = g_tw + tslot * 16;

    #pragma unroll
    for (int p = 0; p < NPOINTS; p++) {
        const int hp4 = h * NPOINTS + p;
        float lx = fminf(fmaxf(rx + pr[hp4 * 2 + 0], 0.f), 1.f);
        float ly = fminf(fmaxf(ry + pr[hp4 * 2 + 1], 0.f), 1.f);
        float sx = lx * (float)(ww - 1);
        float sy = ly * (float)(hh - 1);
        int x0 = (int)floorf(sx); x0 = min(max(x0, 0), ww - 1);
        int y0 = (int)floorf(sy); y0 = min(max(y0, 0), hh - 1);
        int x1 = min(x0 + 1, ww - 1);
        int y1 = min(y0 + 1, hh - 1);
        float wx1 = sx - (float)x0, wx0 = 1.f - wx1;
        float wy1 = sy - (float)y0, wy0 = 1.f - wy1;
        float a = attn[p];
        ti[p * 4 + 0] = vbase + (y0 * ww + x0) * DMODEL;
        ti[p * 4 + 1] = vbase + (y1 * ww + x0) * DMODEL;
        ti[p * 4 + 2] = vbase + (y0 * ww + x1) * DMODEL;
        ti[p * 4 + 3] = vbase + (y1 * ww + x1) * DMODEL;
        tw[p * 4 + 0] = wx0 * wy0 * a;
        tw[p * 4 + 1] = wx0 * wy1 * a;
        tw[p * 4 + 2] = wx1 * wy0 * a;
        tw[p * 4 + 3] = wx1 * wy1 * a;
    }
}

// ---------------------------------------------------------------------------
// Gather (slice): warp = (bq, head), lane = channel; half values, half output.
// ---------------------------------------------------------------------------
__global__ __launch_bounds__(256) void gather_kernel(int wgBase)
{
    const int wg = wgBase + ((blockIdx.x * blockDim.x + threadIdx.x) >> 5);
    const int lane = threadIdx.x & 31;

    const int4* ti = (const int4*)(g_tidx + (long)wg * 16);
    const float4* tw = (const float4*)(g_tw + (long)wg * 16);

    float acc = 0.f;
    #pragma unroll
    for (int c = 0; c < 4; c++) {
        int4 id = ti[c];
        float4 w = tw[c];
        acc = fmaf(w.x, __half2float(g_valh[id.x + lane]), acc);
        acc = fmaf(w.y, __half2float(g_valh[id.y + lane]), acc);
        acc = fmaf(w.z, __half2float(g_valh[id.z + lane]), acc);
        acc = fmaf(w.w, __half2float(g_valh[id.w + lane]), acc);
    }

    const int bq = wg >> 3;
    const int h = wg & 7;
    g_samph[(long)bq * DMODEL + h * DHEAD + lane] = __float2half_rn(acc);
}

// ---------------------------------------------------------------------------
// Launch — R11 topology + tail pipelining (GEMM1 stays monolithic):
//   s0: transpose(Wval), GEMM1, gather half0, gather half1, GEMM4 half1
//   s1: transpose(Wout), proj path, prep_tab; then GEMM4 half0 (after gather0)
// ---------------------------------------------------------------------------
extern "C" void kernel_launch(void* const* d_in, const int* in_sizes, int n_in,
                              void* d_out, int out_size)
{
    const float* query   = (const float*)d_in[0];
    const float* ref_pts = (const float*)d_in[1];
    const float* inp     = (const float*)d_in[2];
    const int*   hp      = (const int*)d_in[3];
    const int*   wp      = (const int*)d_in[4];
    const float* W_off   = (const float*)d_in[5];
    const float* b_off   = (const float*)d_in[6];
    const float* W_attn  = (const float*)d_in[7];
    const float* b_attn  = (const float*)d_in[8];
    const float* W_val   = (const float*)d_in[9];
    const float* b_val   = (const float*)d_in[10];
    const float* W_out   = (const float*)d_in[11];
    const float* b_out   = (const float*)d_in[12];
    float* out = (float*)d_out;

    __half *valh_ptr, *samph_ptr, *wvth_ptr, *woth_ptr;
    float *proj_ptr, *wcat_ptr, *bcat_ptr;
    cudaGetSymbolAddress((void**)&valh_ptr, g_valh);
    cudaGetSymbolAddress((void**)&samph_ptr, g_samph);
    cudaGetSymbolAddress((void**)&proj_ptr, g_proj);
    cudaGetSymbolAddress((void**)&wcat_ptr, g_Wcat);
    cudaGetSymbolAddress((void**)&bcat_ptr, g_bcat);
    cudaGetSymbolAddress((void**)&wvth_ptr, g_WvalTh);
    cudaGetSymbolAddress((void**)&woth_ptr, g_WoutTh);

    static cudaStream_t s1 = nullptr;
    static cudaEvent_t evFork = nullptr, evTab = nullptr, evG0 = nullptr, evEnd = nullptr;
    if (!s1) {
        cudaStreamCreateWithFlags(&s1, cudaStreamNonBlocking);
        cudaEventCreateWithFlags(&evFork, cudaEventDisableTiming);
        cudaEventCreateWithFlags(&evTab, cudaEventDisableTiming);
        cudaEventCreateWithFlags(&evG0, cudaEventDisableTiming);
        cudaEventCreateWithFlags(&evEnd, cudaEventDisableTiming);
        cudaFuncSetAttribute(tf32_split_gemm_kernel,
                             cudaFuncAttributeMaxDynamicSharedMemorySize, GEMM_SMEM_BYTES);
        cudaFuncSetAttribute((fp16_gemm_kernel<false, true>),
                             cudaFuncAttributeMaxDynamicSharedMemorySize, FP16_SMEM_F32A);
        cudaFuncSetAttribute((fp16_gemm_kernel<true, false>),
                             cudaFuncAttributeMaxDynamicSharedMemorySize, FP16_SMEM_H16A);
    }

    const int M1 = BATCH * HWTOT;          // 80000
    const int MQ = BATCH * QLEN;           // 16384
    const int HALF_WG = (MQ / 2) * NHEADS; // warps per half

    // ---- fork: s1 runs the (independent) projection path + Wout transpose
    cudaEventRecord(evFork, 0);
    cudaStreamWaitEvent(s1, evFork, 0);

    transpose_w_kernel<<<64, dim3(32, 8), 0, s1>>>(W_out, woth_ptr);
    prep_wcat_kernel<<<(DMODEL * NPROJ + 255) / 256, 256, 0, s1>>>(
        W_off, b_off, W_attn, b_attn);
    {
        dim3 grid(1, MQ / GBM);
        tf32_split_gemm_kernel<<<grid, 256, GEMM_SMEM_BYTES, s1>>>(
            query, wcat_ptr, bcat_ptr, proj_ptr, MQ, NPROJ, DMODEL);
    }
    prep_tab_kernel<<<MQ / 32, 256, 0, s1>>>(ref_pts, hp, wp);
    cudaEventRecord(evTab, s1);

    // ---- s0: transpose(Wval) then the monolithic value GEMM
    transpose_w_kernel<<<64, dim3(32, 8)>>>(W_val, wvth_ptr);
    {
        dim3 grid(DMODEL / FBN, M1 / FBM);
        fp16_gemm_kernel<false, true><<<grid, 256, FP16_SMEM_F32A>>>(
            inp, wvth_ptr, b_val, valh_ptr, DMODEL, DMODEL);
    }

    // ---- tail pipeline: gather0 | (gather1 || GEMM4h0) | GEMM4h1
    cudaStreamWaitEvent(0, evTab, 0);
    gather_kernel<<<HALF_WG / 8, 256>>>(0);
    cudaEventRecord(evG0, 0);
    gather_kernel<<<HALF_WG / 8, 256>>>(HALF_WG);

    // s1: output GEMM half0 (needs Wout [s1 in-order] + gather0)
    cudaStreamWaitEvent(s1, evG0, 0);
    {
        dim3 grid(DMODEL / FBN, (MQ / 2) / FBM);
        fp16_gemm_kernel<true, false><<<grid, 256, FP16_SMEM_H16A, s1>>>(
            samph_ptr, woth_ptr, b_out, out, DMODEL, DMODEL);
    }
    cudaEventRecord(evEnd, s1);

    // s0: output GEMM half1 (in-order after gather1)
    {
        dim3 grid(DMODEL / FBN, (MQ / 2) / FBM);
        fp16_gemm_kernel<true, false><<<grid, 256, FP16_SMEM_H16A>>>(
            samph_ptr + (long)(MQ / 2) * DMODEL, woth_ptr, b_out,
            out + (long)(MQ / 2) * DMODEL, DMODEL, DMODEL);
    }

    // ---- join
    cudaStreamWaitEvent(0, evEnd, 0);
}

// round 13
// speedup vs baseline: 1.0107x; 1.0107x over previous
#include <cuda_runtime.h>
#include <cuda_fp16.h>
#include <math.h>
#include <stdint.h>

// Problem constants (fixed by the dataset instance)
#define NHEADS 8
#define NPOINTS 4
#define DMODEL 256
#define DHEAD 32
#define BATCH 8
#define QLEN 2048
#define HWTOT 10000
#define NPROJ 96   // 64 offset cols + 32 attn cols

// Scratch (device globals — no allocation allowed)
__device__ __half g_valh[(size_t)BATCH * HWTOT * DMODEL];    // 40.96 MB
__device__ __half g_samph[(size_t)BATCH * QLEN * DMODEL];    //  8.39 MB
__device__ float  g_proj[(size_t)BATCH * QLEN * NPROJ];
__device__ float  g_Wcat[DMODEL * NPROJ];
__device__ float  g_bcat[NPROJ];
__device__ __half g_WvalTh[DMODEL * DMODEL];                 // [N][K] half
__device__ __half g_WoutTh[DMODEL * DMODEL];
__device__ int    g_tidx[(size_t)BATCH * QLEN * NHEADS * 16];
__device__ float  g_tw[(size_t)BATCH * QLEN * NHEADS * 16];

// ---------------------------------------------------------------------------
// helpers
// ---------------------------------------------------------------------------
__device__ __forceinline__ uint32_t f2tf32(float x) {
    uint32_t u;
    asm("cvt.rna.tf32.f32 %0, %1;" : "=r"(u) : "f"(x));
    return u;
}
__device__ __forceinline__ float tf32f(float x) {
    return __uint_as_float(f2tf32(x));
}
__device__ __forceinline__ uint32_t packh2(float x, float y) {
    __half2 h = __floats2half2_rn(x, y);
    return *(uint32_t*)&h;
}

__device__ __forceinline__ void mma16816(float d[4],
                                         uint32_t a0, uint32_t a1, uint32_t a2, uint32_t a3,
                                         uint32_t b0, uint32_t b1) {
    asm volatile(
        "mma.sync.aligned.m16n8k16.row.col.f32.f16.f16.f32 "
        "{%0,%1,%2,%3}, {%4,%5,%6,%7}, {%8,%9}, {%0,%1,%2,%3};"
        : "+f"(d[0]), "+f"(d[1]), "+f"(d[2]), "+f"(d[3])
        : "r"(a0), "r"(a1), "r"(a2), "r"(a3), "r"(b0), "r"(b1));
}
__device__ __forceinline__ void mma8(float d[4],
                                     uint32_t a0, uint32_t a1, uint32_t a2, uint32_t a3,
                                     uint32_t b0, uint32_t b1) {
    asm volatile(
        "mma.sync.aligned.m16n8k8.row.col.f32.tf32.tf32.f32 "
        "{%0,%1,%2,%3}, {%4,%5,%6,%7}, {%8,%9}, {%0,%1,%2,%3};"
        : "+f"(d[0]), "+f"(d[1]), "+f"(d[2]), "+f"(d[3])
        : "r"(a0), "r"(a1), "r"(a2), "r"(a3), "r"(b0), "r"(b1));
}
__device__ __forceinline__ void cpasync16(uint32_t smem_addr, const void* gptr) {
    asm volatile("cp.async.cg.shared.global [%0], [%1], 16;\n"
                 :: "r"(smem_addr), "l"(gptr));
}
__device__ __forceinline__ void cpasync16p(uint32_t smem_addr, const void* gptr, bool valid) {
    int sz = valid ? 16 : 0;
    asm volatile("cp.async.cg.shared.global [%0], [%1], 16, %2;\n"
                 :: "r"(smem_addr), "l"(gptr), "r"(sz));
}
__device__ __forceinline__ void cpasync_commit() {
    asm volatile("cp.async.commit_group;\n" ::);
}
template<int Ncp>
__device__ __forceinline__ void cpasync_wait() {
    asm volatile("cp.async.wait_group %0;\n" :: "n"(Ncp));
}

// ---------------------------------------------------------------------------
// FP16 tensor-core GEMM, cp.async pipeline (4 stages for fp32-A, 3 for half-A).
//   AH = A half in gmem; CH = C stored as half.
// C[M,N] = A[M,K] @ BT^T + bias  (BT half [N,K] row-major).
// Block tile 128x128x32; rows multiple of 128, K%32==0.
// Single barrier per k-iteration.
// ---------------------------------------------------------------------------
#define FBM 128
#define FBN 128
#define FBK 32
#define FSTRF 36   // floats per A row (fp32 variant)
#define FSTRH 40   // halfs per row (half variant / B)

template<bool AH, bool CH>
__global__ __launch_bounds__(256) void fp16_gemm_kernel(
    const void* __restrict__ Av, const __half* __restrict__ BT,
    const float* __restrict__ bias, void* __restrict__ Cv,
    int N, int K)
{
    constexpr int FSTAGES = AH ? 3 : 4;
    extern __shared__ __align__(16) char fsm[];
    const int aStageBytes = AH ? (FBM * FSTRH * 2) : (FBM * FSTRF * 4);
    const int bStageBytes = FBN * FSTRH * 2;
    char* Abase = fsm;
    char* Bbase = fsm + FSTAGES * aStageBytes;

    const int t = threadIdx.x;
    const int warp = t >> 5;
    const int lane = t & 31;
    const int g = lane >> 2;
    const int tig = lane & 3;
    const int wm = (warp >> 1) * 32;
    const int wn = (warp & 1) * 64;

    const int rowTile = blockIdx.y * FBM;
    const int colTile = blockIdx.x * FBN;
    const __half* Bg = BT + (long)colTile * K;

    uint32_t sAaddr[4], sBaddr[2];
    const char* gA[4];
    const __half* gB[2];
    if (AH) {
        const __half* Ag = (const __half*)Av + (long)rowTile * K;
        #pragma unroll
        for (int j = 0; j < 2; j++) {
            const int idx = t + j * 256;
            const int r = idx >> 2;
            const int hc = (idx & 3) * 8;
            sAaddr[j] = (uint32_t)__cvta_generic_to_shared(Abase + (r * FSTRH + hc) * 2);
            gA[j] = (const char*)(Ag + (long)r * K + hc);
        }
    } else {
        const float* Ag = (const float*)Av + (long)rowTile * K;
        #pragma unroll
        for (int j = 0; j < 4; j++) {
            const int idx = t + j * 256;
            const int r = idx >> 3;
            const int fc = idx & 7;
            sAaddr[j] = (uint32_t)__cvta_generic_to_shared(Abase + (r * FSTRF + fc * 4) * 4);
            gA[j] = (const char*)(Ag + (long)r * K + fc * 4);
        }
    }
    #pragma unroll
    for (int j = 0; j < 2; j++) {
        const int idx = t + j * 256;
        const int r = idx >> 2;
        const int hc = (idx & 3) * 8;
        sBaddr[j] = (uint32_t)__cvta_generic_to_shared(Bbase + (r * FSTRH + hc) * 2);
        gB[j] = Bg + (long)r * K + hc;
    }

    const int kIters = K / FBK;
    auto issue_tile = [&](int tile) {
        if (tile < kIters) {
            const int s = tile % FSTAGES;
            const int k0 = tile * FBK;
            if (AH) {
                #pragma unroll
                for (int j = 0; j < 2; j++)
                    cpasync16(sAaddr[j] + s * aStageBytes, gA[j] + (long)k0 * 2);
            } else {
                #pragma unroll
                for (int j = 0; j < 4; j++)
                    cpasync16(sAaddr[j] + s * aStageBytes, gA[j] + (long)k0 * 4);
            }
            #pragma unroll
            for (int j = 0; j < 2; j++)
                cpasync16(sBaddr[j] + s * bStageBytes, gB[j] + k0);
        }
        cpasync_commit();
    };

    float acc[2][8][4];
    #pragma unroll
    for (int i = 0; i < 2; i++)
        #pragma unroll
        for (int j = 0; j < 8; j++)
            #pragma unroll
            for (int r = 0; r < 4; r++) acc[i][j][r] = 0.f;

    #pragma unroll
    for (int s = 0; s < FSTAGES - 1; s++) issue_tile(s);

    #pragma unroll 1
    for (int it = 0; it < kIters; ++it) {
        cpasync_wait<FSTAGES - 2>();
        __syncthreads();   // orders iter it-1's compute before this issue
        issue_tile(it + FSTAGES - 1);

        const int s = it % FSTAGES;
        const __half* BsS = (const __half*)(Bbase + s * bStageBytes);

        #pragma unroll
        for (int ks = 0; ks < 2; ks++) {
            const int kb = ks * 16 + 2 * tig;
            uint32_t af[2][4];
            if (AH) {
                const __half* AsS = (const __half*)(Abase + s * aStageBytes);
                #pragma unroll
                for (int mt = 0; mt < 2; mt++) {
                    const int m0 = wm + mt * 16;
                    af[mt][0] = *(const uint32_t*)&AsS[(m0 + g) * FSTRH + kb];
                    af[mt][1] = *(const uint32_t*)&AsS[(m0 + g + 8) * FSTRH + kb];
                    af[mt][2] = *(const uint32_t*)&AsS[(m0 + g) * FSTRH + kb + 8];
                    af[mt][3] = *(const uint32_t*)&AsS[(m0 + g + 8) * FSTRH + kb + 8];
                }
            } else {
                const float* AsS = (const float*)(Abase + s * aStageBytes);
                #pragma unroll
                for (int mt = 0; mt < 2; mt++) {
                    const int m0 = wm + mt * 16;
                    float2 v0 = *(const float2*)&AsS[(m0 + g) * FSTRF + kb];
                    float2 v1 = *(const float2*)&AsS[(m0 + g + 8) * FSTRF + kb];
                    float2 v2 = *(const float2*)&AsS[(m0 + g) * FSTRF + kb + 8];
                    float2 v3 = *(const float2*)&AsS[(m0 + g + 8) * FSTRF + kb + 8];
                    af[mt][0] = packh2(v0.x, v0.y);
                    af[mt][1] = packh2(v1.x, v1.y);
                    af[mt][2] = packh2(v2.x, v2.y);
                    af[mt][3] = packh2(v3.x, v3.y);
                }
            }
            uint32_t bf[8][2];
            #pragma unroll
            for (int nt = 0; nt < 8; nt++) {
                const int n0 = wn + nt * 8;
                bf[nt][0] = *(const uint32_t*)&BsS[(n0 + g) * FSTRH + kb];
                bf[nt][1] = *(const uint32_t*)&BsS[(n0 + g) * FSTRH + kb + 8];
            }
            #pragma unroll
            for (int mt = 0; mt < 2; mt++)
                #pragma unroll
                for (int nt = 0; nt < 8; nt++)
                    mma16816(acc[mt][nt], af[mt][0], af[mt][1], af[mt][2], af[mt][3],
                             bf[nt][0], bf[nt][1]);
        }
    }

    #pragma unroll
    for (int mt = 0; mt < 2; mt++) {
        #pragma unroll
        for (int nt = 0; nt < 8; nt++) {
            const int c = colTile + wn + nt * 8 + tig * 2;
            const float b0 = bias[c], b1 = bias[c + 1];
            const int r0 = rowTile + wm + mt * 16 + g;
            if (CH) {
                __half* C = (__half*)Cv;
                *(__half2*)(C + (long)r0 * N + c) =
                    __floats2half2_rn(acc[mt][nt][0] + b0, acc[mt][nt][1] + b1);
                *(__half2*)(C + (long)(r0 + 8) * N + c) =
                    __floats2half2_rn(acc[mt][nt][2] + b0, acc[mt][nt][3] + b1);
            } else {
                float* C = (float*)Cv;
                *(float2*)(C + (long)r0 * N + c) =
                    make_float2(acc[mt][nt][0] + b0, acc[mt][nt][1] + b1);
                *(float2*)(C + (long)(r0 + 8) * N + c) =
                    make_float2(acc[mt][nt][2] + b0, acc[mt][nt][3] + b1);
            }
        }
    }
}

#define FP16_SMEM_F32A (4 * (FBM * FSTRF * 4 + FBN * FSTRH * 2))   // 4-stage: 113,664
#define FP16_SMEM_H16A (3 * (FBM * FSTRH * 2 + FBN * FSTRH * 2))   // 3-stage: 61,440

// ---------------------------------------------------------------------------
// mma.sync 3xTF32 split GEMM (precision-critical offset/attn projection only).
// ---------------------------------------------------------------------------
#define GBM 128
#define GBN 128
#define GBK 16
#define STAGES 4
#define AS_STRIDE 20
#define BS_STRIDE 132
#define GEMM_SMEM_BYTES (STAGES * (GBM * AS_STRIDE + GBK * BS_STRIDE) * 4)

__global__ __launch_bounds__(256) void tf32_split_gemm_kernel(
    const float* __restrict__ A, const float* __restrict__ B,
    const float* __restrict__ bias, float* __restrict__ C,
    int M, int N, int K)
{
    extern __shared__ __align__(16) float dsmf[];
    float* As = dsmf;
    float* Bs = dsmf + STAGES * GBM * AS_STRIDE;

    const int t = threadIdx.x;
    const int warp = t >> 5;
    const int lane = t & 31;
    const int g = lane >> 2;
    const int tig = lane & 3;
    const int wm = (warp >> 1) * 32;
    const int wn = (warp & 1) * 64;

    const int rowTile = blockIdx.y * GBM;
    const int colTile = blockIdx.x * GBN;

    const int ar0 = t >> 2;
    const int ar1 = ar0 + 64;
    const int ac = (t & 3) * 4;
    const int bk0 = t >> 5;
    const int bk1 = bk0 + 8;
    const int bc = (t & 31) * 4;

    const bool aok0 = (rowTile + ar0) < M;
    const bool aok1 = (rowTile + ar1) < M;
    const bool bok = (colTile + bc) < N;

    const float* Ap0 = A + (long)(rowTile + ar0) * K + ac;
    const float* Ap1 = A + (long)(rowTile + ar1) * K + ac;
    const float* Bp0 = B + (long)bk0 * N + colTile + bc;
    const float* Bp1 = B + (long)bk1 * N + colTile + bc;

    const uint32_t aStageB = GBM * AS_STRIDE * 4;
    const uint32_t bStageB = GBK * BS_STRIDE * 4;
    const uint32_t sA0 = (uint32_t)__cvta_generic_to_shared(As + ar0 * AS_STRIDE + ac);
    const uint32_t sA1 = (uint32_t)__cvta_generic_to_shared(As + ar1 * AS_STRIDE + ac);
    const uint32_t sB0 = (uint32_t)__cvta_generic_to_shared(Bs + bk0 * BS_STRIDE + bc);
    const uint32_t sB1 = (uint32_t)__cvta_generic_to_shared(Bs + bk1 * BS_STRIDE + bc);

    const int kIters = K / GBK;

    auto issue_tile = [&](int tile) {
        if (tile < kIters) {
            const int s = tile % STAGES;
            const long k0 = (long)tile * GBK;
            cpasync16p(sA0 + s * aStageB, Ap0 + k0, aok0);
            cpasync16p(sA1 + s * aStageB, Ap1 + k0, aok1);
            cpasync16p(sB0 + s * bStageB, Bp0 + k0 * N, bok);
            cpasync16p(sB1 + s * bStageB, Bp1 + k0 * N, bok);
        }
        cpasync_commit();
    };

    float acc[2][8][4];
    #pragma unroll
    for (int i = 0; i < 2; i++)
        #pragma unroll
        for (int j = 0; j < 8; j++)
            #pragma unroll
            for (int r = 0; r < 4; r++) acc[i][j][r] = 0.f;

    #pragma unroll
    for (int s = 0; s < STAGES - 1; s++) issue_tile(s);

    #pragma unroll 1
    for (int it = 0; it < kIters; ++it) {
        cpasync_wait<STAGES - 2>();
        __syncthreads();
        issue_tile(it + STAGES - 1);

        const int s = it % STAGES;
        const float* AsS = As + s * GBM * AS_STRIDE;
        const float* BsS = Bs + s * GBK * BS_STRIDE;

        #pragma unroll
        for (int kk = 0; kk < GBK; kk += 8) {
            float ar[2][4];
            #pragma unroll
            for (int mt = 0; mt < 2; mt++) {
                const int m0 = wm + mt * 16;
                ar[mt][0] = AsS[(m0 + g) * AS_STRIDE + kk + tig];
                ar[mt][1] = AsS[(m0 + g + 8) * AS_STRIDE + kk + tig];
                ar[mt][2] = AsS[(m0 + g) * AS_STRIDE + kk + tig + 4];
                ar[mt][3] = AsS[(m0 + g + 8) * AS_STRIDE + kk + tig + 4];
            }
            float br[8][2];
            #pragma unroll
            for (int nt = 0; nt < 8; nt++) {
                br[nt][0] = BsS[(kk + tig) * BS_STRIDE + wn + nt * 8 + g];
                br[nt][1] = BsS[(kk + tig + 4) * BS_STRIDE + wn + nt * 8 + g];
            }
            uint32_t ahi[2][4], alo[2][4];
            #pragma unroll
            for (int mt = 0; mt < 2; mt++)
                #pragma unroll
                for (int r = 0; r < 4; r++) {
                    float hi = tf32f(ar[mt][r]);
                    ahi[mt][r] = __float_as_uint(hi);
                    alo[mt][r] = f2tf32(ar[mt][r] - hi);
                }
            uint32_t bhi[8][2], blo[8][2];
            #pragma unroll
            for (int nt = 0; nt < 8; nt++)
                #pragma unroll
                for (int r = 0; r < 2; r++) {
                    float hi = tf32f(br[nt][r]);
                    bhi[nt][r] = __float_as_uint(hi);
                    blo[nt][r] = f2tf32(br[nt][r] - hi);
                }
            #pragma unroll
            for (int mt = 0; mt < 2; mt++)
                #pragma unroll
                for (int nt = 0; nt < 8; nt++) {
                    mma8(acc[mt][nt], ahi[mt][0], ahi[mt][1], ahi[mt][2], ahi[mt][3],
                         blo[nt][0], blo[nt][1]);
                    mma8(acc[mt][nt], alo[mt][0], alo[mt][1], alo[mt][2], alo[mt][3],
                         bhi[nt][0], bhi[nt][1]);
                    mma8(acc[mt][nt], ahi[mt][0], ahi[mt][1], ahi[mt][2], ahi[mt][3],
                         bhi[nt][0], bhi[nt][1]);
                }
        }
        __syncthreads();
    }

    #pragma unroll
    for (int mt = 0; mt < 2; mt++) {
        #pragma unroll
        for (int nt = 0; nt < 8; nt++) {
            const int c = colTile + wn + nt * 8 + tig * 2;
            if (c >= N) continue;
            const float b0 = bias[c], b1 = bias[c + 1];
            const int r0 = rowTile + wm + mt * 16 + g;
            if (r0 < M) {
                float2 v = make_float2(acc[mt][nt][0] + b0, acc[mt][nt][1] + b1);
                *(float2*)(C + (long)r0 * N + c) = v;
            }
            const int r1 = r0 + 8;
            if (r1 < M) {
                float2 v = make_float2(acc[mt][nt][2] + b0, acc[mt][nt][3] + b1);
                *(float2*)(C + (long)r1 * N + c) = v;
            }
        }
    }
}

// ---------------------------------------------------------------------------
// Prep kernels
// ---------------------------------------------------------------------------
__global__ void prep_wcat_kernel(const float* __restrict__ W_off, const float* __restrict__ b_off,
                                 const float* __restrict__ W_attn, const float* __restrict__ b_attn)
{
    int i = blockIdx.x * blockDim.x + threadIdx.x;
    if (i < DMODEL * NPROJ) {
        int k = i / NPROJ, n = i % NPROJ;
        g_Wcat[i] = (n < 64) ? W_off[k * 64 + n] : W_attn[k * 32 + (n - 64)];
    }
    if (i < NPROJ) g_bcat[i] = (i < 64) ? b_off[i] : b_attn[i - 64];
}

// Transpose one 256x256 fp32 matrix into half [N][K].
__global__ void transpose_w_kernel(const float* __restrict__ W, __half* __restrict__ T)
{
    __shared__ float t[32][33];
    const int bi = blockIdx.x;
    const int tx = bi & 7, ty = bi >> 3;
    int x = tx * 32 + threadIdx.x;
    int y = ty * 32 + threadIdx.y;
    #pragma unroll
    for (int i = 0; i < 32; i += 8)
        t[threadIdx.y + i][threadIdx.x] = W[(y + i) * DMODEL + x];
    __syncthreads();
    x = ty * 32 + threadIdx.x;
    y = tx * 32 + threadIdx.y;
    #pragma unroll
    for (int i = 0; i < 32; i += 8)
        T[(y + i) * DMODEL + x] = __float2half_rn(t[threadIdx.x][threadIdx.y + i]);
}

// ---------------------------------------------------------------------------
// Prep table: coalesced smem staging of g_proj; thread = (bq_local, head).
// ---------------------------------------------------------------------------
__global__ __launch_bounds__(256) void prep_tab_kernel(
    const float* __restrict__ ref_pts,
    const int* __restrict__ hp, const int* __restrict__ wp)
{
    __shared__ float sproj[32 * NPROJ];
    __shared__ float sref[64];

    const int tid = threadIdx.x;
    const int bq0 = blockIdx.x * 32;

    #pragma unroll
    for (int j = 0; j < 12; j++)
        sproj[tid + j * 256] = g_proj[(long)bq0 * NPROJ + tid + j * 256];
    if (tid < 64) sref[tid] = ref_pts[(long)bq0 * 2 + tid];
    __syncthreads();

    const int bql = tid >> 3;
    const int h = tid & 7;
    const int bq = bq0 + bql;
    const int b = bq / QLEN;
    const float* pr = sproj + bql * NPROJ;

    float l0 = pr[64 + h * 4 + 0], l1 = pr[64 + h * 4 + 1];
    float l2 = pr[64 + h * 4 + 2], l3 = pr[64 + h * 4 + 3];
    float m = fmaxf(fmaxf(l0, l1), fmaxf(l2, l3));
    float e0 = expf(l0 - m), e1 = expf(l1 - m), e2 = expf(l2 - m), e3 = expf(l3 - m);
    float inv = 1.f / (e0 + e1 + e2 + e3);
    float attn[NPOINTS] = { e0 * inv, e1 * inv, e2 * inv, e3 * inv };

    const int ww = *wp;
    const int hh = *hp;
    const float rx = sref[bql * 2 + 0];
    const float ry = sref[bql * 2 + 1];
    const int vbase = b * HWTOT * DMODEL + h * DHEAD;

    const long tslot = (long)bq * NHEADS + h;
    int* ti = g_tidx + tslot * 16;
    float* tw = g_tw + tslot * 16;

    #pragma unroll
    for (int p = 0; p < NPOINTS; p++) {
        const int hp4 = h * NPOINTS + p;
        float lx = fminf(fmaxf(rx + pr[hp4 * 2 + 0], 0.f), 1.f);
        float ly = fminf(fmaxf(ry + pr[hp4 * 2 + 1], 0.f), 1.f);
        float sx = lx * (float)(ww - 1);
        float sy = ly * (float)(hh - 1);
        int x0 = (int)floorf(sx); x0 = min(max(x0, 0), ww - 1);
        int y0 = (int)floorf(sy); y0 = min(max(y0, 0), hh - 1);
        int x1 = min(x0 + 1, ww - 1);
        int y1 = min(y0 + 1, hh - 1);
        float wx1 = sx - (float)x0, wx0 = 1.f - wx1;
        float wy1 = sy - (float)y0, wy0 = 1.f - wy1;
        float a = attn[p];
        ti[p * 4 + 0] = vbase + (y0 * ww + x0) * DMODEL;
        ti[p * 4 + 1] = vbase + (y1 * ww + x0) * DMODEL;
        ti[p * 4 + 2] = vbase + (y0 * ww + x1) * DMODEL;
        ti[p * 4 + 3] = vbase + (y1 * ww + x1) * DMODEL;
        tw[p * 4 + 0] = wx0 * wy0 * a;
        tw[p * 4 + 1] = wx0 * wy1 * a;
        tw[p * 4 + 2] = wx1 * wy0 * a;
        tw[p * 4 + 3] = wx1 * wy1 * a;
    }
}

// ---------------------------------------------------------------------------
// Gather: warp = (bq, head), lane = channel; half values, half output.
// ---------------------------------------------------------------------------
__global__ __launch_bounds__(256) void gather_kernel()
{
    const int wg = (blockIdx.x * blockDim.x + threadIdx.x) >> 5;
    const int lane = threadIdx.x & 31;
    if (wg >= BATCH * QLEN * NHEADS) return;

    const int4* ti = (const int4*)(g_tidx + (long)wg * 16);
    const float4* tw = (const float4*)(g_tw + (long)wg * 16);

    float acc = 0.f;
    #pragma unroll
    for (int c = 0; c < 4; c++) {
        int4 id = ti[c];
        float4 w = tw[c];
        acc = fmaf(w.x, __half2float(g_valh[id.x + lane]), acc);
        acc = fmaf(w.y, __half2float(g_valh[id.y + lane]), acc);
        acc = fmaf(w.z, __half2float(g_valh[id.z + lane]), acc);
        acc = fmaf(w.w, __half2float(g_valh[id.w + lane]), acc);
    }

    const int bq = wg >> 3;
    const int h = wg & 7;
    g_samph[(long)bq * DMODEL + h * DHEAD + lane] = __float2half_rn(acc);
}

// ---------------------------------------------------------------------------
// Launch — R11 topology; only change: transpose(Wout) lives on s1.
//   s0: transpose(Wval), GEMM1, gather, GEMM4   (monolithic tail)
//   s1: transpose(Wout), proj path, prep_tab
// ---------------------------------------------------------------------------
extern "C" void kernel_launch(void* const* d_in, const int* in_sizes, int n_in,
                              void* d_out, int out_size)
{
    const float* query   = (const float*)d_in[0];
    const float* ref_pts = (const float*)d_in[1];
    const float* inp     = (const float*)d_in[2];
    const int*   hp      = (const int*)d_in[3];
    const int*   wp      = (const int*)d_in[4];
    const float* W_off   = (const float*)d_in[5];
    const float* b_off   = (const float*)d_in[6];
    const float* W_attn  = (const float*)d_in[7];
    const float* b_attn  = (const float*)d_in[8];
    const float* W_val   = (const float*)d_in[9];
    const float* b_val   = (const float*)d_in[10];
    const float* W_out   = (const float*)d_in[11];
    const float* b_out   = (const float*)d_in[12];
    float* out = (float*)d_out;

    __half *valh_ptr, *samph_ptr, *wvth_ptr, *woth_ptr;
    float *proj_ptr, *wcat_ptr, *bcat_ptr;
    cudaGetSymbolAddress((void**)&valh_ptr, g_valh);
    cudaGetSymbolAddress((void**)&samph_ptr, g_samph);
    cudaGetSymbolAddress((void**)&proj_ptr, g_proj);
    cudaGetSymbolAddress((void**)&wcat_ptr, g_Wcat);
    cudaGetSymbolAddress((void**)&bcat_ptr, g_bcat);
    cudaGetSymbolAddress((void**)&wvth_ptr, g_WvalTh);
    cudaGetSymbolAddress((void**)&woth_ptr, g_WoutTh);

    static cudaStream_t s1 = nullptr;
    static cudaEvent_t evFork = nullptr, evJoin = nullptr;
    if (!s1) {
        cudaStreamCreateWithFlags(&s1, cudaStreamNonBlocking);
        cudaEventCreateWithFlags(&evFork, cudaEventDisableTiming);
        cudaEventCreateWithFlags(&evJoin, cudaEventDisableTiming);
        cudaFuncSetAttribute(tf32_split_gemm_kernel,
                             cudaFuncAttributeMaxDynamicSharedMemorySize, GEMM_SMEM_BYTES);
        cudaFuncSetAttribute((fp16_gemm_kernel<false, true>),
                             cudaFuncAttributeMaxDynamicSharedMemorySize, FP16_SMEM_F32A);
        cudaFuncSetAttribute((fp16_gemm_kernel<true, false>),
                             cudaFuncAttributeMaxDynamicSharedMemorySize, FP16_SMEM_H16A);
    }

    const int M1 = BATCH * HWTOT;   // 80000
    const int MQ = BATCH * QLEN;    // 16384

    // ---- fork: s1 runs the (independent) projection path + Wout transpose
    cudaEventRecord(evFork, 0);
    cudaStreamWaitEvent(s1, evFork, 0);

    transpose_w_kernel<<<64, dim3(32, 8), 0, s1>>>(W_out, woth_ptr);
    prep_wcat_kernel<<<(DMODEL * NPROJ + 255) / 256, 256, 0, s1>>>(
        W_off, b_off, W_attn, b_attn);
    {
        dim3 grid(1, MQ / GBM);
        tf32_split_gemm_kernel<<<grid, 256, GEMM_SMEM_BYTES, s1>>>(
            query, wcat_ptr, bcat_ptr, proj_ptr, MQ, NPROJ, DMODEL);
    }
    prep_tab_kernel<<<MQ / 32, 256, 0, s1>>>(ref_pts, hp, wp);
    cudaEventRecord(evJoin, s1);

    // ---- s0: transpose(Wval), then the monolithic value GEMM
    transpose_w_kernel<<<64, dim3(32, 8)>>>(W_val, wvth_ptr);
    {
        dim3 grid(DMODEL / FBN, M1 / FBM);
        fp16_gemm_kernel<false, true><<<grid, 256, FP16_SMEM_F32A>>>(
            inp, wvth_ptr, b_val, valh_ptr, DMODEL, DMODEL);
    }

    // ---- join: gather needs values (s0) + table (s1); Wout done on s1 earlier
    cudaStreamWaitEvent(0, evJoin, 0);
    gather_kernel<<<(MQ * NHEADS) / 8, 256>>>();

    // out = sampled(h) @ W_out + b_out   (pure half GEMM, fp32 out)
    {
        dim3 grid(DMODEL / FBN, MQ / FBM);
        fp16_gemm_kernel<true, false><<<grid, 256, FP16_SMEM_H16A>>>(
            samph_ptr, woth_ptr, b_out, out, DMODEL, DMODEL);
    }
}

// round 16
// speedup vs baseline: 1.1794x; 1.1669x over previous
#include <cuda_runtime.h>
#include <cuda_fp16.h>
#include <math.h>
#include <stdint.h>

// Problem constants (fixed by the dataset instance)
#define NHEADS 8
#define NPOINTS 4
#define DMODEL 256
#define DHEAD 32
#define BATCH 8
#define QLEN 2048
#define HWTOT 10000
#define NPROJ 96   // 64 offset cols + 32 attn cols

// Scratch (device globals — no allocation allowed)
__device__ __half g_valh[(size_t)BATCH * HWTOT * DMODEL];    // 40.96 MB
__device__ __half g_samph[(size_t)BATCH * QLEN * DMODEL];    //  8.39 MB
__device__ float  g_proj[(size_t)BATCH * QLEN * NPROJ];
__device__ float  g_Wcat[DMODEL * NPROJ];
__device__ float  g_bcat[NPROJ];
__device__ __half g_WvalTh[DMODEL * DMODEL];                 // [N][K] half
__device__ __half g_WoutTh[DMODEL * DMODEL];
__device__ int    g_tidx[(size_t)BATCH * QLEN * NHEADS * 16];
__device__ float  g_tw[(size_t)BATCH * QLEN * NHEADS * 16];

// ---------------------------------------------------------------------------
// helpers
// ---------------------------------------------------------------------------
__device__ __forceinline__ uint32_t f2tf32(float x) {
    uint32_t u;
    asm("cvt.rna.tf32.f32 %0, %1;" : "=r"(u) : "f"(x));
    return u;
}
__device__ __forceinline__ float tf32f(float x) {
    return __uint_as_float(f2tf32(x));
}
__device__ __forceinline__ uint32_t packh2(float x, float y) {
    __half2 h = __floats2half2_rn(x, y);
    return *(uint32_t*)&h;
}

__device__ __forceinline__ void mma16816(float d[4],
                                         uint32_t a0, uint32_t a1, uint32_t a2, uint32_t a3,
                                         uint32_t b0, uint32_t b1) {
    asm volatile(
        "mma.sync.aligned.m16n8k16.row.col.f32.f16.f16.f32 "
        "{%0,%1,%2,%3}, {%4,%5,%6,%7}, {%8,%9}, {%0,%1,%2,%3};"
        : "+f"(d[0]), "+f"(d[1]), "+f"(d[2]), "+f"(d[3])
        : "r"(a0), "r"(a1), "r"(a2), "r"(a3), "r"(b0), "r"(b1));
}
__device__ __forceinline__ void mma8(float d[4],
                                     uint32_t a0, uint32_t a1, uint32_t a2, uint32_t a3,
                                     uint32_t b0, uint32_t b1) {
    asm volatile(
        "mma.sync.aligned.m16n8k8.row.col.f32.tf32.tf32.f32 "
        "{%0,%1,%2,%3}, {%4,%5,%6,%7}, {%8,%9}, {%0,%1,%2,%3};"
        : "+f"(d[0]), "+f"(d[1]), "+f"(d[2]), "+f"(d[3])
        : "r"(a0), "r"(a1), "r"(a2), "r"(a3), "r"(b0), "r"(b1));
}
__device__ __forceinline__ void cpasync16(uint32_t smem_addr, const void* gptr) {
    asm volatile("cp.async.cg.shared.global [%0], [%1], 16;\n"
                 :: "r"(smem_addr), "l"(gptr));
}
__device__ __forceinline__ void cpasync16p(uint32_t smem_addr, const void* gptr, bool valid) {
    int sz = valid ? 16 : 0;
    asm volatile("cp.async.cg.shared.global [%0], [%1], 16, %2;\n"
                 :: "r"(smem_addr), "l"(gptr), "r"(sz));
}
__device__ __forceinline__ void cpasync_commit() {
    asm volatile("cp.async.commit_group;\n" ::);
}
template<int Ncp>
__device__ __forceinline__ void cpasync_wait() {
    asm volatile("cp.async.wait_group %0;\n" :: "n"(Ncp));
}

// ---------------------------------------------------------------------------
// FP16 tensor-core GEMM, cp.async 3-stage pipeline, single barrier per k-iter,
// 2 CTAs/SM (smem 86KB, regs capped via launch_bounds).
//   AH = A half in gmem; CH = C stored as half.
// C[M,N] = A[M,K] @ BT^T + bias  (BT half [N,K] row-major).
// Block tile 128x128x32; rows multiple of 128, K%32==0.
// ---------------------------------------------------------------------------
#define FBM 128
#define FBN 128
#define FBK 32
#define FSTAGES 3
#define FSTRF 36   // floats per A row (fp32 variant)
#define FSTRH 40   // halfs per row (half variant / B)

template<bool AH, bool CH>
__global__ __launch_bounds__(256, 2) void fp16_gemm_kernel(
    const void* __restrict__ Av, const __half* __restrict__ BT,
    const float* __restrict__ bias, void* __restrict__ Cv,
    int N, int K)
{
    extern __shared__ __align__(16) char fsm[];
    const int aStageBytes = AH ? (FBM * FSTRH * 2) : (FBM * FSTRF * 4);
    const int bStageBytes = FBN * FSTRH * 2;
    char* Abase = fsm;
    char* Bbase = fsm + FSTAGES * aStageBytes;

    const int t = threadIdx.x;
    const int warp = t >> 5;
    const int lane = t & 31;
    const int g = lane >> 2;
    const int tig = lane & 3;
    const int wm = (warp >> 1) * 32;
    const int wn = (warp & 1) * 64;

    const int rowTile = blockIdx.y * FBM;
    const int colTile = blockIdx.x * FBN;
    const __half* Bg = BT + (long)colTile * K;

    uint32_t sAaddr[4], sBaddr[2];
    const char* gA[4];
    const __half* gB[2];
    if (AH) {
        const __half* Ag = (const __half*)Av + (long)rowTile * K;
        #pragma unroll
        for (int j = 0; j < 2; j++) {
            const int idx = t + j * 256;
            const int r = idx >> 2;
            const int hc = (idx & 3) * 8;
            sAaddr[j] = (uint32_t)__cvta_generic_to_shared(Abase + (r * FSTRH + hc) * 2);
            gA[j] = (const char*)(Ag + (long)r * K + hc);
        }
    } else {
        const float* Ag = (const float*)Av + (long)rowTile * K;
        #pragma unroll
        for (int j = 0; j < 4; j++) {
            const int idx = t + j * 256;
            const int r = idx >> 3;
            const int fc = idx & 7;
            sAaddr[j] = (uint32_t)__cvta_generic_to_shared(Abase + (r * FSTRF + fc * 4) * 4);
            gA[j] = (const char*)(Ag + (long)r * K + fc * 4);
        }
    }
    #pragma unroll
    for (int j = 0; j < 2; j++) {
        const int idx = t + j * 256;
        const int r = idx >> 2;
        const int hc = (idx & 3) * 8;
        sBaddr[j] = (uint32_t)__cvta_generic_to_shared(Bbase + (r * FSTRH + hc) * 2);
        gB[j] = Bg + (long)r * K + hc;
    }

    const int kIters = K / FBK;
    auto issue_tile = [&](int tile) {
        if (tile < kIters) {
            const int s = tile % FSTAGES;
            const int k0 = tile * FBK;
            if (AH) {
                #pragma unroll
                for (int j = 0; j < 2; j++)
                    cpasync16(sAaddr[j] + s * aStageBytes, gA[j] + (long)k0 * 2);
            } else {
                #pragma unroll
                for (int j = 0; j < 4; j++)
                    cpasync16(sAaddr[j] + s * aStageBytes, gA[j] + (long)k0 * 4);
            }
            #pragma unroll
            for (int j = 0; j < 2; j++)
                cpasync16(sBaddr[j] + s * bStageBytes, gB[j] + k0);
        }
        cpasync_commit();
    };

    float acc[2][8][4];
    #pragma unroll
    for (int i = 0; i < 2; i++)
        #pragma unroll
        for (int j = 0; j < 8; j++)
            #pragma unroll
            for (int r = 0; r < 4; r++) acc[i][j][r] = 0.f;

    #pragma unroll
    for (int s = 0; s < FSTAGES - 1; s++) issue_tile(s);

    #pragma unroll 1
    for (int it = 0; it < kIters; ++it) {
        cpasync_wait<FSTAGES - 2>();
        __syncthreads();   // orders iter it-1's compute before this issue
        issue_tile(it + FSTAGES - 1);

        const int s = it % FSTAGES;
        const __half* BsS = (const __half*)(Bbase + s * bStageBytes);

        #pragma unroll
        for (int ks = 0; ks < 2; ks++) {
            const int kb = ks * 16 + 2 * tig;
            uint32_t af[2][4];
            if (AH) {
                const __half* AsS = (const __half*)(Abase + s * aStageBytes);
                #pragma unroll
                for (int mt = 0; mt < 2; mt++) {
                    const int m0 = wm + mt * 16;
                    af[mt][0] = *(const uint32_t*)&AsS[(m0 + g) * FSTRH + kb];
                    af[mt][1] = *(const uint32_t*)&AsS[(m0 + g + 8) * FSTRH + kb];
                    af[mt][2] = *(const uint32_t*)&AsS[(m0 + g) * FSTRH + kb + 8];
                    af[mt][3] = *(const uint32_t*)&AsS[(m0 + g + 8) * FSTRH + kb + 8];
                }
            } else {
                const float* AsS = (const float*)(Abase + s * aStageBytes);
                #pragma unroll
                for (int mt = 0; mt < 2; mt++) {
                    const int m0 = wm + mt * 16;
                    float2 v0 = *(const float2*)&AsS[(m0 + g) * FSTRF + kb];
                    float2 v1 = *(const float2*)&AsS[(m0 + g + 8) * FSTRF + kb];
                    float2 v2 = *(const float2*)&AsS[(m0 + g) * FSTRF + kb + 8];
                    float2 v3 = *(const float2*)&AsS[(m0 + g + 8) * FSTRF + kb + 8];
                    af[mt][0] = packh2(v0.x, v0.y);
                    af[mt][1] = packh2(v1.x, v1.y);
                    af[mt][2] = packh2(v2.x, v2.y);
                    af[mt][3] = packh2(v3.x, v3.y);
                }
            }
            uint32_t bf[8][2];
            #pragma unroll
            for (int nt = 0; nt < 8; nt++) {
                const int n0 = wn + nt * 8;
                bf[nt][0] = *(const uint32_t*)&BsS[(n0 + g) * FSTRH + kb];
                bf[nt][1] = *(const uint32_t*)&BsS[(n0 + g) * FSTRH + kb + 8];
            }
            #pragma unroll
            for (int mt = 0; mt < 2; mt++)
                #pragma unroll
                for (int nt = 0; nt < 8; nt++)
                    mma16816(acc[mt][nt], af[mt][0], af[mt][1], af[mt][2], af[mt][3],
                             bf[nt][0], bf[nt][1]);
        }
    }

    #pragma unroll
    for (int mt = 0; mt < 2; mt++) {
        #pragma unroll
        for (int nt = 0; nt < 8; nt++) {
            const int c = colTile + wn + nt * 8 + tig * 2;
            const float b0 = bias[c], b1 = bias[c + 1];
            const int r0 = rowTile + wm + mt * 16 + g;
            if (CH) {
                __half* C = (__half*)Cv;
                *(__half2*)(C + (long)r0 * N + c) =
                    __floats2half2_rn(acc[mt][nt][0] + b0, acc[mt][nt][1] + b1);
                *(__half2*)(C + (long)(r0 + 8) * N + c) =
                    __floats2half2_rn(acc[mt][nt][2] + b0, acc[mt][nt][3] + b1);
            } else {
                float* C = (float*)Cv;
                *(float2*)(C + (long)r0 * N + c) =
                    make_float2(acc[mt][nt][0] + b0, acc[mt][nt][1] + b1);
                *(float2*)(C + (long)(r0 + 8) * N + c) =
                    make_float2(acc[mt][nt][2] + b0, acc[mt][nt][3] + b1);
            }
        }
    }
}

#define FP16_SMEM_F32A (FSTAGES * (FBM * FSTRF * 4 + FBN * FSTRH * 2))   // 86,016 -> 2 CTA/SM
#define FP16_SMEM_H16A (FSTAGES * (FBM * FSTRH * 2 + FBN * FSTRH * 2))   // 61,440

// ---------------------------------------------------------------------------
// mma.sync 3xTF32 split GEMM (precision-critical offset/attn projection only).
// ---------------------------------------------------------------------------
#define GBM 128
#define GBN 128
#define GBK 16
#define STAGES 4
#define AS_STRIDE 20
#define BS_STRIDE 132
#define GEMM_SMEM_BYTES (STAGES * (GBM * AS_STRIDE + GBK * BS_STRIDE) * 4)

__global__ __launch_bounds__(256) void tf32_split_gemm_kernel(
    const float* __restrict__ A, const float* __restrict__ B,
    const float* __restrict__ bias, float* __restrict__ C,
    int M, int N, int K)
{
    extern __shared__ __align__(16) float dsmf[];
    float* As = dsmf;
    float* Bs = dsmf + STAGES * GBM * AS_STRIDE;

    const int t = threadIdx.x;
    const int warp = t >> 5;
    const int lane = t & 31;
    const int g = lane >> 2;
    const int tig = lane & 3;
    const int wm = (warp >> 1) * 32;
    const int wn = (warp & 1) * 64;

    const int rowTile = blockIdx.y * GBM;
    const int colTile = blockIdx.x * GBN;

    const int ar0 = t >> 2;
    const int ar1 = ar0 + 64;
    const int ac = (t & 3) * 4;
    const int bk0 = t >> 5;
    const int bk1 = bk0 + 8;
    const int bc = (t & 31) * 4;

    const bool aok0 = (rowTile + ar0) < M;
    const bool aok1 = (rowTile + ar1) < M;
    const bool bok = (colTile + bc) < N;

    const float* Ap0 = A + (long)(rowTile + ar0) * K + ac;
    const float* Ap1 = A + (long)(rowTile + ar1) * K + ac;
    const float* Bp0 = B + (long)bk0 * N + colTile + bc;
    const float* Bp1 = B + (long)bk1 * N + colTile + bc;

    const uint32_t aStageB = GBM * AS_STRIDE * 4;
    const uint32_t bStageB = GBK * BS_STRIDE * 4;
    const uint32_t sA0 = (uint32_t)__cvta_generic_to_shared(As + ar0 * AS_STRIDE + ac);
    const uint32_t sA1 = (uint32_t)__cvta_generic_to_shared(As + ar1 * AS_STRIDE + ac);
    const uint32_t sB0 = (uint32_t)__cvta_generic_to_shared(Bs + bk0 * BS_STRIDE + bc);
    const uint32_t sB1 = (uint32_t)__cvta_generic_to_shared(Bs + bk1 * BS_STRIDE + bc);

    const int kIters = K / GBK;

    auto issue_tile = [&](int tile) {
        if (tile < kIters) {
            const int s = tile % STAGES;
            const long k0 = (long)tile * GBK;
            cpasync16p(sA0 + s * aStageB, Ap0 + k0, aok0);
            cpasync16p(sA1 + s * aStageB, Ap1 + k0, aok1);
            cpasync16p(sB0 + s * bStageB, Bp0 + k0 * N, bok);
            cpasync16p(sB1 + s * bStageB, Bp1 + k0 * N, bok);
        }
        cpasync_commit();
    };

    float acc[2][8][4];
    #pragma unroll
    for (int i = 0; i < 2; i++)
        #pragma unroll
        for (int j = 0; j < 8; j++)
            #pragma unroll
            for (int r = 0; r < 4; r++) acc[i][j][r] = 0.f;

    #pragma unroll
    for (int s = 0; s < STAGES - 1; s++) issue_tile(s);

    #pragma unroll 1
    for (int it = 0; it < kIters; ++it) {
        cpasync_wait<STAGES - 2>();
        __syncthreads();
        issue_tile(it + STAGES - 1);

        const int s = it % STAGES;
        const float* AsS = As + s * GBM * AS_STRIDE;
        const float* BsS = Bs + s * GBK * BS_STRIDE;

        #pragma unroll
        for (int kk = 0; kk < GBK; kk += 8) {
            float ar[2][4];
            #pragma unroll
            for (int mt = 0; mt < 2; mt++) {
                const int m0 = wm + mt * 16;
                ar[mt][0] = AsS[(m0 + g) * AS_STRIDE + kk + tig];
                ar[mt][1] = AsS[(m0 + g + 8) * AS_STRIDE + kk + tig];
                ar[mt][2] = AsS[(m0 + g) * AS_STRIDE + kk + tig + 4];
                ar[mt][3] = AsS[(m0 + g + 8) * AS_STRIDE + kk + tig + 4];
            }
            float br[8][2];
            #pragma unroll
            for (int nt = 0; nt < 8; nt++) {
                br[nt][0] = BsS[(kk + tig) * BS_STRIDE + wn + nt * 8 + g];
                br[nt][1] = BsS[(kk + tig + 4) * BS_STRIDE + wn + nt * 8 + g];
            }
            uint32_t ahi[2][4], alo[2][4];
            #pragma unroll
            for (int mt = 0; mt < 2; mt++)
                #pragma unroll
                for (int r = 0; r < 4; r++) {
                    float hi = tf32f(ar[mt][r]);
                    ahi[mt][r] = __float_as_uint(hi);
                    alo[mt][r] = f2tf32(ar[mt][r] - hi);
                }
            uint32_t bhi[8][2], blo[8][2];
            #pragma unroll
            for (int nt = 0; nt < 8; nt++)
                #pragma unroll
                for (int r = 0; r < 2; r++) {
                    float hi = tf32f(br[nt][r]);
                    bhi[nt][r] = __float_as_uint(hi);
                    blo[nt][r] = f2tf32(br[nt][r] - hi);
                }
            #pragma unroll
            for (int mt = 0; mt < 2; mt++)
                #pragma unroll
                for (int nt = 0; nt < 8; nt++) {
                    mma8(acc[mt][nt], ahi[mt][0], ahi[mt][1], ahi[mt][2], ahi[mt][3],
                         blo[nt][0], blo[nt][1]);
                    mma8(acc[mt][nt], alo[mt][0], alo[mt][1], alo[mt][2], alo[mt][3],
                         bhi[nt][0], bhi[nt][1]);
                    mma8(acc[mt][nt], ahi[mt][0], ahi[mt][1], ahi[mt][2], ahi[mt][3],
                         bhi[nt][0], bhi[nt][1]);
                }
        }
        __syncthreads();
    }

    #pragma unroll
    for (int mt = 0; mt < 2; mt++) {
        #pragma unroll
        for (int nt = 0; nt < 8; nt++) {
            const int c = colTile + wn + nt * 8 + tig * 2;
            if (c >= N) continue;
            const float b0 = bias[c], b1 = bias[c + 1];
            const int r0 = rowTile + wm + mt * 16 + g;
            if (r0 < M) {
                float2 v = make_float2(acc[mt][nt][0] + b0, acc[mt][nt][1] + b1);
                *(float2*)(C + (long)r0 * N + c) = v;
            }
            const int r1 = r0 + 8;
            if (r1 < M) {
                float2 v = make_float2(acc[mt][nt][2] + b0, acc[mt][nt][3] + b1);
                *(float2*)(C + (long)r1 * N + c) = v;
            }
        }
    }
}

// ---------------------------------------------------------------------------
// Prep kernels
// ---------------------------------------------------------------------------
__global__ void prep_wcat_kernel(const float* __restrict__ W_off, const float* __restrict__ b_off,
                                 const float* __restrict__ W_attn, const float* __restrict__ b_attn)
{
    int i = blockIdx.x * blockDim.x + threadIdx.x;
    if (i < DMODEL * NPROJ) {
        int k = i / NPROJ, n = i % NPROJ;
        g_Wcat[i] = (n < 64) ? W_off[k * 64 + n] : W_attn[k * 32 + (n - 64)];
    }
    if (i < NPROJ) g_bcat[i] = (i < 64) ? b_off[i] : b_attn[i - 64];
}

// Transpose one 256x256 fp32 matrix into half [N][K].
__global__ void transpose_w_kernel(const float* __restrict__ W, __half* __restrict__ T)
{
    __shared__ float t[32][33];
    const int bi = blockIdx.x;
    const int tx = bi & 7, ty = bi >> 3;
    int x = tx * 32 + threadIdx.x;
    int y = ty * 32 + threadIdx.y;
    #pragma unroll
    for (int i = 0; i < 32; i += 8)
        t[threadIdx.y + i][threadIdx.x] = W[(y + i) * DMODEL + x];
    __syncthreads();
    x = ty * 32 + threadIdx.x;
    y = tx * 32 + threadIdx.y;
    #pragma unroll
    for (int i = 0; i < 32; i += 8)
        T[(y + i) * DMODEL + x] = __float2half_rn(t[threadIdx.x][threadIdx.y + i]);
}

// ---------------------------------------------------------------------------
// Prep table: coalesced smem staging of g_proj; thread = (bq_local, head).
// ---------------------------------------------------------------------------
__global__ __launch_bounds__(256) void prep_tab_kernel(
    const float* __restrict__ ref_pts,
    const int* __restrict__ hp, const int* __restrict__ wp)
{
    __shared__ float sproj[32 * NPROJ];
    __shared__ float sref[64];

    const int tid = threadIdx.x;
    const int bq0 = blockIdx.x * 32;

    #pragma unroll
    for (int j = 0; j < 12; j++)
        sproj[tid + j * 256] = g_proj[(long)bq0 * NPROJ + tid + j * 256];
    if (tid < 64) sref[tid] = ref_pts[(long)bq0 * 2 + tid];
    __syncthreads();

    const int bql = tid >> 3;
    const int h = tid & 7;
    const int bq = bq0 + bql;
    const int b = bq / QLEN;
    const float* pr = sproj + bql * NPROJ;

    float l0 = pr[64 + h * 4 + 0], l1 = pr[64 + h * 4 + 1];
    float l2 = pr[64 + h * 4 + 2], l3 = pr[64 + h * 4 + 3];
    float m = fmaxf(fmaxf(l0, l1), fmaxf(l2, l3));
    float e0 = expf(l0 - m), e1 = expf(l1 - m), e2 = expf(l2 - m), e3 = expf(l3 - m);
    float inv = 1.f / (e0 + e1 + e2 + e3);
    float attn[NPOINTS] = { e0 * inv, e1 * inv, e2 * inv, e3 * inv };

    const int ww = *wp;
    const int hh = *hp;
    const float rx = sref[bql * 2 + 0];
    const float ry = sref[bql * 2 + 1];
    const int vbase = b * HWTOT * DMODEL + h * DHEAD;

    const long tslot = (long)bq * NHEADS + h;
    int* ti = g_tidx + tslot * 16;
    float* tw = g_tw + tslot * 16;

    #pragma unroll
    for (int p = 0; p < NPOINTS; p++) {
        const int hp4 = h * NPOINTS + p;
        float lx = fminf(fmaxf(rx + pr[hp4 * 2 + 0], 0.f), 1.f);
        float ly = fminf(fmaxf(ry + pr[hp4 * 2 + 1], 0.f), 1.f);
        float sx = lx * (float)(ww - 1);
        float sy = ly * (float)(hh - 1);
        int x0 = (int)floorf(sx); x0 = min(max(x0, 0), ww - 1);
        int y0 = (int)floorf(sy); y0 = min(max(y0, 0), hh - 1);
        int x1 = min(x0 + 1, ww - 1);
        int y1 = min(y0 + 1, hh - 1);
        float wx1 = sx - (float)x0, wx0 = 1.f - wx1;
        float wy1 = sy - (float)y0, wy0 = 1.f - wy1;
        float a = attn[p];
        ti[p * 4 + 0] = vbase + (y0 * ww + x0) * DMODEL;
        ti[p * 4 + 1] = vbase + (y1 * ww + x0) * DMODEL;
        ti[p * 4 + 2] = vbase + (y0 * ww + x1) * DMODEL;
        ti[p * 4 + 3] = vbase + (y1 * ww + x1) * DMODEL;
        tw[p * 4 + 0] = wx0 * wy0 * a;
        tw[p * 4 + 1] = wx0 * wy1 * a;
        tw[p * 4 + 2] = wx1 * wy0 * a;
        tw[p * 4 + 3] = wx1 * wy1 * a;
    }
}

// ---------------------------------------------------------------------------
// Gather: warp = (bq, head), lane = channel; half values, half output.
// ---------------------------------------------------------------------------
__global__ __launch_bounds__(256) void gather_kernel()
{
    const int wg = (blockIdx.x * blockDim.x + threadIdx.x) >> 5;
    const int lane = threadIdx.x & 31;
    if (wg >= BATCH * QLEN * NHEADS) return;

    const int4* ti = (const int4*)(g_tidx + (long)wg * 16);
    const float4* tw = (const float4*)(g_tw + (long)wg * 16);

    float acc = 0.f;
    #pragma unroll
    for (int c = 0; c < 4; c++) {
        int4 id = ti[c];
        float4 w = tw[c];
        acc = fmaf(w.x, __half2float(g_valh[id.x + lane]), acc);
        acc = fmaf(w.y, __half2float(g_valh[id.y + lane]), acc);
        acc = fmaf(w.z, __half2float(g_valh[id.z + lane]), acc);
        acc = fmaf(w.w, __half2float(g_valh[id.w + lane]), acc);
    }

    const int bq = wg >> 3;
    const int h = wg & 7;
    g_samph[(long)bq * DMODEL + h * DHEAD + lane] = __float2half_rn(acc);
}

// ---------------------------------------------------------------------------
// Launch — R11 topology exactly:
//   s0: transpose(Wval), transpose(Wout), GEMM1, gather, GEMM4
//   s1: proj path (wcat, proj GEMM, prep_tab)
// ---------------------------------------------------------------------------
extern "C" void kernel_launch(void* const* d_in, const int* in_sizes, int n_in,
                              void* d_out, int out_size)
{
    const float* query   = (const float*)d_in[0];
    const float* ref_pts = (const float*)d_in[1];
    const float* inp     = (const float*)d_in[2];
    const int*   hp      = (const int*)d_in[3];
    const int*   wp      = (const int*)d_in[4];
    const float* W_off   = (const float*)d_in[5];
    const float* b_off   = (const float*)d_in[6];
    const float* W_attn  = (const float*)d_in[7];
    const float* b_attn  = (const float*)d_in[8];
    const float* W_val   = (const float*)d_in[9];
    const float* b_val   = (const float*)d_in[10];
    const float* W_out   = (const float*)d_in[11];
    const float* b_out   = (const float*)d_in[12];
    float* out = (float*)d_out;

    __half *valh_ptr, *samph_ptr, *wvth_ptr, *woth_ptr;
    float *proj_ptr, *wcat_ptr, *bcat_ptr;
    cudaGetSymbolAddress((void**)&valh_ptr, g_valh);
    cudaGetSymbolAddress((void**)&samph_ptr, g_samph);
    cudaGetSymbolAddress((void**)&proj_ptr, g_proj);
    cudaGetSymbolAddress((void**)&wcat_ptr, g_Wcat);
    cudaGetSymbolAddress((void**)&bcat_ptr, g_bcat);
    cudaGetSymbolAddress((void**)&wvth_ptr, g_WvalTh);
    cudaGetSymbolAddress((void**)&woth_ptr, g_WoutTh);

    static cudaStream_t s1 = nullptr;
    static cudaEvent_t evFork = nullptr, evJoin = nullptr;
    if (!s1) {
        cudaStreamCreateWithFlags(&s1, cudaStreamNonBlocking);
        cudaEventCreateWithFlags(&evFork, cudaEventDisableTiming);
        cudaEventCreateWithFlags(&evJoin, cudaEventDisableTiming);
        cudaFuncSetAttribute(tf32_split_gemm_kernel,
                             cudaFuncAttributeMaxDynamicSharedMemorySize, GEMM_SMEM_BYTES);
        cudaFuncSetAttribute((fp16_gemm_kernel<false, true>),
                             cudaFuncAttributeMaxDynamicSharedMemorySize, FP16_SMEM_F32A);
        cudaFuncSetAttribute((fp16_gemm_kernel<true, false>),
                             cudaFuncAttributeMaxDynamicSharedMemorySize, FP16_SMEM_H16A);
    }

    const int M1 = BATCH * HWTOT;   // 80000
    const int MQ = BATCH * QLEN;    // 16384

    // ---- fork: s1 runs the (independent) projection path
    cudaEventRecord(evFork, 0);
    cudaStreamWaitEvent(s1, evFork, 0);

    prep_wcat_kernel<<<(DMODEL * NPROJ + 255) / 256, 256, 0, s1>>>(
        W_off, b_off, W_attn, b_attn);
    {
        dim3 grid(1, MQ / GBM);
        tf32_split_gemm_kernel<<<grid, 256, GEMM_SMEM_BYTES, s1>>>(
            query, wcat_ptr, bcat_ptr, proj_ptr, MQ, NPROJ, DMODEL);
    }
    prep_tab_kernel<<<MQ / 32, 256, 0, s1>>>(ref_pts, hp, wp);
    cudaEventRecord(evJoin, s1);

    // ---- s0: transposes, then the monolithic value GEMM
    transpose_w_kernel<<<64, dim3(32, 8)>>>(W_val, wvth_ptr);
    transpose_w_kernel<<<64, dim3(32, 8)>>>(W_out, woth_ptr);
    {
        dim3 grid(DMODEL / FBN, M1 / FBM);
        fp16_gemm_kernel<false, true><<<grid, 256, FP16_SMEM_F32A>>>(
            inp, wvth_ptr, b_val, valh_ptr, DMODEL, DMODEL);
    }

    // ---- join: gather needs values (s0) + table (s1)
    cudaStreamWaitEvent(0, evJoin, 0);
    gather_kernel<<<(MQ * NHEADS) / 8, 256>>>();

    // out = sampled(h) @ W_out + b_out   (pure half GEMM, fp32 out)
    {
        dim3 grid(DMODEL / FBN, MQ / FBM);
        fp16_gemm_kernel<true, false><<<grid, 256, FP16_SMEM_H16A>>>(
            samph_ptr, woth_ptr, b_out, out, DMODEL, DMODEL);
    }
}

// round 17
// speedup vs baseline: 1.1967x; 1.0147x over previous
#include <cuda_runtime.h>
#include <cuda_fp16.h>
#include <math.h>
#include <stdint.h>

// Problem constants (fixed by the dataset instance)
#define NHEADS 8
#define NPOINTS 4
#define DMODEL 256
#define DHEAD 32
#define BATCH 8
#define QLEN 2048
#define HWTOT 10000
#define NPROJ 96   // 64 offset cols + 32 attn cols

// Scratch (device globals — no allocation allowed)
__device__ __half g_valh[(size_t)BATCH * HWTOT * DMODEL];    // 40.96 MB
__device__ __half g_samph[(size_t)BATCH * QLEN * DMODEL];    //  8.39 MB
__device__ float  g_proj[(size_t)BATCH * QLEN * NPROJ];
__device__ float  g_Wcat[DMODEL * NPROJ];
__device__ float  g_bcat[NPROJ];
__device__ __half g_WvalTh[DMODEL * DMODEL];                 // [N][K] half
__device__ __half g_WoutTh[DMODEL * DMODEL];
__device__ int    g_tidx[(size_t)BATCH * QLEN * NHEADS * 16];
__device__ float  g_tw[(size_t)BATCH * QLEN * NHEADS * 16];

// ---------------------------------------------------------------------------
// helpers
// ---------------------------------------------------------------------------
__device__ __forceinline__ uint32_t f2tf32(float x) {
    uint32_t u;
    asm("cvt.rna.tf32.f32 %0, %1;" : "=r"(u) : "f"(x));
    return u;
}
__device__ __forceinline__ float tf32f(float x) {
    return __uint_as_float(f2tf32(x));
}
__device__ __forceinline__ uint32_t packh2(float x, float y) {
    __half2 h = __floats2half2_rn(x, y);
    return *(uint32_t*)&h;
}

__device__ __forceinline__ void mma16816(float d[4],
                                         uint32_t a0, uint32_t a1, uint32_t a2, uint32_t a3,
                                         uint32_t b0, uint32_t b1) {
    asm volatile(
        "mma.sync.aligned.m16n8k16.row.col.f32.f16.f16.f32 "
        "{%0,%1,%2,%3}, {%4,%5,%6,%7}, {%8,%9}, {%0,%1,%2,%3};"
        : "+f"(d[0]), "+f"(d[1]), "+f"(d[2]), "+f"(d[3])
        : "r"(a0), "r"(a1), "r"(a2), "r"(a3), "r"(b0), "r"(b1));
}
__device__ __forceinline__ void mma8(float d[4],
                                     uint32_t a0, uint32_t a1, uint32_t a2, uint32_t a3,
                                     uint32_t b0, uint32_t b1) {
    asm volatile(
        "mma.sync.aligned.m16n8k8.row.col.f32.tf32.tf32.f32 "
        "{%0,%1,%2,%3}, {%4,%5,%6,%7}, {%8,%9}, {%0,%1,%2,%3};"
        : "+f"(d[0]), "+f"(d[1]), "+f"(d[2]), "+f"(d[3])
        : "r"(a0), "r"(a1), "r"(a2), "r"(a3), "r"(b0), "r"(b1));
}
__device__ __forceinline__ void cpasync16(uint32_t smem_addr, const void* gptr) {
    asm volatile("cp.async.cg.shared.global [%0], [%1], 16;\n"
                 :: "r"(smem_addr), "l"(gptr));
}
__device__ __forceinline__ void cpasync16p(uint32_t smem_addr, const void* gptr, bool valid) {
    int sz = valid ? 16 : 0;
    asm volatile("cp.async.cg.shared.global [%0], [%1], 16, %2;\n"
                 :: "r"(smem_addr), "l"(gptr), "r"(sz));
}
__device__ __forceinline__ void cpasync_commit() {
    asm volatile("cp.async.commit_group;\n" ::);
}
template<int Ncp>
__device__ __forceinline__ void cpasync_wait() {
    asm volatile("cp.async.wait_group %0;\n" :: "n"(Ncp));
}

// ---------------------------------------------------------------------------
// FP16 tensor-core GEMM, cp.async 3-stage pipeline, single barrier per k-iter,
// 2 CTAs/SM (smem 86KB, regs capped via launch_bounds).
//   AH = A half in gmem; CH = C stored as half.
// C[M,N] = A[M,K] @ BT^T + bias  (BT half [N,K] row-major).
// Block tile 128x128x32; rows multiple of 128, K%32==0.
// ---------------------------------------------------------------------------
#define FBM 128
#define FBN 128
#define FBK 32
#define FSTAGES 3
#define FSTRF 36   // floats per A row (fp32 variant)
#define FSTRH 40   // halfs per row (half variant / B)

template<bool AH, bool CH>
__global__ __launch_bounds__(256, 2) void fp16_gemm_kernel(
    const void* __restrict__ Av, const __half* __restrict__ BT,
    const float* __restrict__ bias, void* __restrict__ Cv,
    int N, int K)
{
    extern __shared__ __align__(16) char fsm[];
    const int aStageBytes = AH ? (FBM * FSTRH * 2) : (FBM * FSTRF * 4);
    const int bStageBytes = FBN * FSTRH * 2;
    char* Abase = fsm;
    char* Bbase = fsm + FSTAGES * aStageBytes;

    const int t = threadIdx.x;
    const int warp = t >> 5;
    const int lane = t & 31;
    const int g = lane >> 2;
    const int tig = lane & 3;
    const int wm = (warp >> 1) * 32;
    const int wn = (warp & 1) * 64;

    const int rowTile = blockIdx.y * FBM;
    const int colTile = blockIdx.x * FBN;
    const __half* Bg = BT + (long)colTile * K;

    uint32_t sAaddr[4], sBaddr[2];
    const char* gA[4];
    const __half* gB[2];
    if (AH) {
        const __half* Ag = (const __half*)Av + (long)rowTile * K;
        #pragma unroll
        for (int j = 0; j < 2; j++) {
            const int idx = t + j * 256;
            const int r = idx >> 2;
            const int hc = (idx & 3) * 8;
            sAaddr[j] = (uint32_t)__cvta_generic_to_shared(Abase + (r * FSTRH + hc) * 2);
            gA[j] = (const char*)(Ag + (long)r * K + hc);
        }
    } else {
        const float* Ag = (const float*)Av + (long)rowTile * K;
        #pragma unroll
        for (int j = 0; j < 4; j++) {
            const int idx = t + j * 256;
            const int r = idx >> 3;
            const int fc = idx & 7;
            sAaddr[j] = (uint32_t)__cvta_generic_to_shared(Abase + (r * FSTRF + fc * 4) * 4);
            gA[j] = (const char*)(Ag + (long)r * K + fc * 4);
        }
    }
    #pragma unroll
    for (int j = 0; j < 2; j++) {
        const int idx = t + j * 256;
        const int r = idx >> 2;
        const int hc = (idx & 3) * 8;
        sBaddr[j] = (uint32_t)__cvta_generic_to_shared(Bbase + (r * FSTRH + hc) * 2);
        gB[j] = Bg + (long)r * K + hc;
    }

    const int kIters = K / FBK;
    auto issue_tile = [&](int tile) {
        if (tile < kIters) {
            const int s = tile % FSTAGES;
            const int k0 = tile * FBK;
            if (AH) {
                #pragma unroll
                for (int j = 0; j < 2; j++)
                    cpasync16(sAaddr[j] + s * aStageBytes, gA[j] + (long)k0 * 2);
            } else {
                #pragma unroll
                for (int j = 0; j < 4; j++)
                    cpasync16(sAaddr[j] + s * aStageBytes, gA[j] + (long)k0 * 4);
            }
            #pragma unroll
            for (int j = 0; j < 2; j++)
                cpasync16(sBaddr[j] + s * bStageBytes, gB[j] + k0);
        }
        cpasync_commit();
    };

    float acc[2][8][4];
    #pragma unroll
    for (int i = 0; i < 2; i++)
        #pragma unroll
        for (int j = 0; j < 8; j++)
            #pragma unroll
            for (int r = 0; r < 4; r++) acc[i][j][r] = 0.f;

    #pragma unroll
    for (int s = 0; s < FSTAGES - 1; s++) issue_tile(s);

    #pragma unroll 1
    for (int it = 0; it < kIters; ++it) {
        cpasync_wait<FSTAGES - 2>();
        __syncthreads();   // orders iter it-1's compute before this issue
        issue_tile(it + FSTAGES - 1);

        const int s = it % FSTAGES;
        const __half* BsS = (const __half*)(Bbase + s * bStageBytes);

        #pragma unroll
        for (int ks = 0; ks < 2; ks++) {
            const int kb = ks * 16 + 2 * tig;
            uint32_t af[2][4];
            if (AH) {
                const __half* AsS = (const __half*)(Abase + s * aStageBytes);
                #pragma unroll
                for (int mt = 0; mt < 2; mt++) {
                    const int m0 = wm + mt * 16;
                    af[mt][0] = *(const uint32_t*)&AsS[(m0 + g) * FSTRH + kb];
                    af[mt][1] = *(const uint32_t*)&AsS[(m0 + g + 8) * FSTRH + kb];
                    af[mt][2] = *(const uint32_t*)&AsS[(m0 + g) * FSTRH + kb + 8];
                    af[mt][3] = *(const uint32_t*)&AsS[(m0 + g + 8) * FSTRH + kb + 8];
                }
            } else {
                const float* AsS = (const float*)(Abase + s * aStageBytes);
                #pragma unroll
                for (int mt = 0; mt < 2; mt++) {
                    const int m0 = wm + mt * 16;
                    float2 v0 = *(const float2*)&AsS[(m0 + g) * FSTRF + kb];
                    float2 v1 = *(const float2*)&AsS[(m0 + g + 8) * FSTRF + kb];
                    float2 v2 = *(const float2*)&AsS[(m0 + g) * FSTRF + kb + 8];
                    float2 v3 = *(const float2*)&AsS[(m0 + g + 8) * FSTRF + kb + 8];
                    af[mt][0] = packh2(v0.x, v0.y);
                    af[mt][1] = packh2(v1.x, v1.y);
                    af[mt][2] = packh2(v2.x, v2.y);
                    af[mt][3] = packh2(v3.x, v3.y);
                }
            }
            uint32_t bf[8][2];
            #pragma unroll
            for (int nt = 0; nt < 8; nt++) {
                const int n0 = wn + nt * 8;
                bf[nt][0] = *(const uint32_t*)&BsS[(n0 + g) * FSTRH + kb];
                bf[nt][1] = *(const uint32_t*)&BsS[(n0 + g) * FSTRH + kb + 8];
            }
            #pragma unroll
            for (int mt = 0; mt < 2; mt++)
                #pragma unroll
                for (int nt = 0; nt < 8; nt++)
                    mma16816(acc[mt][nt], af[mt][0], af[mt][1], af[mt][2], af[mt][3],
                             bf[nt][0], bf[nt][1]);
        }
    }

    #pragma unroll
    for (int mt = 0; mt < 2; mt++) {
        #pragma unroll
        for (int nt = 0; nt < 8; nt++) {
            const int c = colTile + wn + nt * 8 + tig * 2;
            const float b0 = bias[c], b1 = bias[c + 1];
            const int r0 = rowTile + wm + mt * 16 + g;
            if (CH) {
                __half* C = (__half*)Cv;
                *(__half2*)(C + (long)r0 * N + c) =
                    __floats2half2_rn(acc[mt][nt][0] + b0, acc[mt][nt][1] + b1);
                *(__half2*)(C + (long)(r0 + 8) * N + c) =
                    __floats2half2_rn(acc[mt][nt][2] + b0, acc[mt][nt][3] + b1);
            } else {
                float* C = (float*)Cv;
                *(float2*)(C + (long)r0 * N + c) =
                    make_float2(acc[mt][nt][0] + b0, acc[mt][nt][1] + b1);
                *(float2*)(C + (long)(r0 + 8) * N + c) =
                    make_float2(acc[mt][nt][2] + b0, acc[mt][nt][3] + b1);
            }
        }
    }
}

#define FP16_SMEM_F32A (FSTAGES * (FBM * FSTRF * 4 + FBN * FSTRH * 2))   // 86,016 -> 2 CTA/SM
#define FP16_SMEM_H16A (FSTAGES * (FBM * FSTRH * 2 + FBN * FSTRH * 2))   // 61,440

// ---------------------------------------------------------------------------
// mma.sync 3xTF32 split GEMM (precision-critical offset/attn projection only).
// ---------------------------------------------------------------------------
#define GBM 128
#define GBN 128
#define GBK 16
#define STAGES 4
#define AS_STRIDE 20
#define BS_STRIDE 132
#define GEMM_SMEM_BYTES (STAGES * (GBM * AS_STRIDE + GBK * BS_STRIDE) * 4)

__global__ __launch_bounds__(256) void tf32_split_gemm_kernel(
    const float* __restrict__ A, const float* __restrict__ B,
    const float* __restrict__ bias, float* __restrict__ C,
    int M, int N, int K)
{
    extern __shared__ __align__(16) float dsmf[];
    float* As = dsmf;
    float* Bs = dsmf + STAGES * GBM * AS_STRIDE;

    const int t = threadIdx.x;
    const int warp = t >> 5;
    const int lane = t & 31;
    const int g = lane >> 2;
    const int tig = lane & 3;
    const int wm = (warp >> 1) * 32;
    const int wn = (warp & 1) * 64;

    const int rowTile = blockIdx.y * GBM;
    const int colTile = blockIdx.x * GBN;

    const int ar0 = t >> 2;
    const int ar1 = ar0 + 64;
    const int ac = (t & 3) * 4;
    const int bk0 = t >> 5;
    const int bk1 = bk0 + 8;
    const int bc = (t & 31) * 4;

    const bool aok0 = (rowTile + ar0) < M;
    const bool aok1 = (rowTile + ar1) < M;
    const bool bok = (colTile + bc) < N;

    const float* Ap0 = A + (long)(rowTile + ar0) * K + ac;
    const float* Ap1 = A + (long)(rowTile + ar1) * K + ac;
    const float* Bp0 = B + (long)bk0 * N + colTile + bc;
    const float* Bp1 = B + (long)bk1 * N + colTile + bc;

    const uint32_t aStageB = GBM * AS_STRIDE * 4;
    const uint32_t bStageB = GBK * BS_STRIDE * 4;
    const uint32_t sA0 = (uint32_t)__cvta_generic_to_shared(As + ar0 * AS_STRIDE + ac);
    const uint32_t sA1 = (uint32_t)__cvta_generic_to_shared(As + ar1 * AS_STRIDE + ac);
    const uint32_t sB0 = (uint32_t)__cvta_generic_to_shared(Bs + bk0 * BS_STRIDE + bc);
    const uint32_t sB1 = (uint32_t)__cvta_generic_to_shared(Bs + bk1 * BS_STRIDE + bc);

    const int kIters = K / GBK;

    auto issue_tile = [&](int tile) {
        if (tile < kIters) {
            const int s = tile % STAGES;
            const long k0 = (long)tile * GBK;
            cpasync16p(sA0 + s * aStageB, Ap0 + k0, aok0);
            cpasync16p(sA1 + s * aStageB, Ap1 + k0, aok1);
            cpasync16p(sB0 + s * bStageB, Bp0 + k0 * N, bok);
            cpasync16p(sB1 + s * bStageB, Bp1 + k0 * N, bok);
        }
        cpasync_commit();
    };

    float acc[2][8][4];
    #pragma unroll
    for (int i = 0; i < 2; i++)
        #pragma unroll
        for (int j = 0; j < 8; j++)
            #pragma unroll
            for (int r = 0; r < 4; r++) acc[i][j][r] = 0.f;

    #pragma unroll
    for (int s = 0; s < STAGES - 1; s++) issue_tile(s);

    #pragma unroll 1
    for (int it = 0; it < kIters; ++it) {
        cpasync_wait<STAGES - 2>();
        __syncthreads();
        issue_tile(it + STAGES - 1);

        const int s = it % STAGES;
        const float* AsS = As + s * GBM * AS_STRIDE;
        const float* BsS = Bs + s * GBK * BS_STRIDE;

        #pragma unroll
        for (int kk = 0; kk < GBK; kk += 8) {
            float ar[2][4];
            #pragma unroll
            for (int mt = 0; mt < 2; mt++) {
                const int m0 = wm + mt * 16;
                ar[mt][0] = AsS[(m0 + g) * AS_STRIDE + kk + tig];
                ar[mt][1] = AsS[(m0 + g + 8) * AS_STRIDE + kk + tig];
                ar[mt][2] = AsS[(m0 + g) * AS_STRIDE + kk + tig + 4];
                ar[mt][3] = AsS[(m0 + g + 8) * AS_STRIDE + kk + tig + 4];
            }
            float br[8][2];
            #pragma unroll
            for (int nt = 0; nt < 8; nt++) {
                br[nt][0] = BsS[(kk + tig) * BS_STRIDE + wn + nt * 8 + g];
                br[nt][1] = BsS[(kk + tig + 4) * BS_STRIDE + wn + nt * 8 + g];
            }
            uint32_t ahi[2][4], alo[2][4];
            #pragma unroll
            for (int mt = 0; mt < 2; mt++)
                #pragma unroll
                for (int r = 0; r < 4; r++) {
                    float hi = tf32f(ar[mt][r]);
                    ahi[mt][r] = __float_as_uint(hi);
                    alo[mt][r] = f2tf32(ar[mt][r] - hi);
                }
            uint32_t bhi[8][2], blo[8][2];
            #pragma unroll
            for (int nt = 0; nt < 8; nt++)
                #pragma unroll
                for (int r = 0; r < 2; r++) {
                    float hi = tf32f(br[nt][r]);
                    bhi[nt][r] = __float_as_uint(hi);
                    blo[nt][r] = f2tf32(br[nt][r] - hi);
                }
            #pragma unroll
            for (int mt = 0; mt < 2; mt++)
                #pragma unroll
                for (int nt = 0; nt < 8; nt++) {
                    mma8(acc[mt][nt], ahi[mt][0], ahi[mt][1], ahi[mt][2], ahi[mt][3],
                         blo[nt][0], blo[nt][1]);
                    mma8(acc[mt][nt], alo[mt][0], alo[mt][1], alo[mt][2], alo[mt][3],
                         bhi[nt][0], bhi[nt][1]);
                    mma8(acc[mt][nt], ahi[mt][0], ahi[mt][1], ahi[mt][2], ahi[mt][3],
                         bhi[nt][0], bhi[nt][1]);
                }
        }
        __syncthreads();
    }

    #pragma unroll
    for (int mt = 0; mt < 2; mt++) {
        #pragma unroll
        for (int nt = 0; nt < 8; nt++) {
            const int c = colTile + wn + nt * 8 + tig * 2;
            if (c >= N) continue;
            const float b0 = bias[c], b1 = bias[c + 1];
            const int r0 = rowTile + wm + mt * 16 + g;
            if (r0 < M) {
                float2 v = make_float2(acc[mt][nt][0] + b0, acc[mt][nt][1] + b1);
                *(float2*)(C + (long)r0 * N + c) = v;
            }
            const int r1 = r0 + 8;
            if (r1 < M) {
                float2 v = make_float2(acc[mt][nt][2] + b0, acc[mt][nt][3] + b1);
                *(float2*)(C + (long)r1 * N + c) = v;
            }
        }
    }
}

// ---------------------------------------------------------------------------
// Prep kernels
// ---------------------------------------------------------------------------
__global__ void prep_wcat_kernel(const float* __restrict__ W_off, const float* __restrict__ b_off,
                                 const float* __restrict__ W_attn, const float* __restrict__ b_attn)
{
    int i = blockIdx.x * blockDim.x + threadIdx.x;
    if (i < DMODEL * NPROJ) {
        int k = i / NPROJ, n = i % NPROJ;
        g_Wcat[i] = (n < 64) ? W_off[k * 64 + n] : W_attn[k * 32 + (n - 64)];
    }
    if (i < NPROJ) g_bcat[i] = (i < 64) ? b_off[i] : b_attn[i - 64];
}

// Transpose both 256x256 fp32 weight matrices into half [N][K] in ONE launch.
// blocks 0..63 -> W_val, 64..127 -> W_out.
__global__ void transpose_both_kernel(const float* __restrict__ Wv, const float* __restrict__ Wo)
{
    __shared__ float t[32][33];
    const int which = blockIdx.x >> 6;
    const int bi = blockIdx.x & 63;
    const int tx = bi & 7, ty = bi >> 3;
    const float* W = which ? Wo : Wv;
    __half* T = which ? g_WoutTh : g_WvalTh;
    int x = tx * 32 + threadIdx.x;
    int y = ty * 32 + threadIdx.y;
    #pragma unroll
    for (int i = 0; i < 32; i += 8)
        t[threadIdx.y + i][threadIdx.x] = W[(y + i) * DMODEL + x];
    __syncthreads();
    x = ty * 32 + threadIdx.x;
    y = tx * 32 + threadIdx.y;
    #pragma unroll
    for (int i = 0; i < 32; i += 8)
        T[(y + i) * DMODEL + x] = __float2half_rn(t[threadIdx.x][threadIdx.y + i]);
}

// ---------------------------------------------------------------------------
// Prep table: coalesced smem staging of g_proj; thread = (bq_local, head).
// ---------------------------------------------------------------------------
__global__ __launch_bounds__(256) void prep_tab_kernel(
    const float* __restrict__ ref_pts,
    const int* __restrict__ hp, const int* __restrict__ wp)
{
    __shared__ float sproj[32 * NPROJ];
    __shared__ float sref[64];

    const int tid = threadIdx.x;
    const int bq0 = blockIdx.x * 32;

    #pragma unroll
    for (int j = 0; j < 12; j++)
        sproj[tid + j * 256] = g_proj[(long)bq0 * NPROJ + tid + j * 256];
    if (tid < 64) sref[tid] = ref_pts[(long)bq0 * 2 + tid];
    __syncthreads();

    const int bql = tid >> 3;
    const int h = tid & 7;
    const int bq = bq0 + bql;
    const int b = bq / QLEN;
    const float* pr = sproj + bql * NPROJ;

    float l0 = pr[64 + h * 4 + 0], l1 = pr[64 + h * 4 + 1];
    float l2 = pr[64 + h * 4 + 2], l3 = pr[64 + h * 4 + 3];
    float m = fmaxf(fmaxf(l0, l1), fmaxf(l2, l3));
    float e0 = expf(l0 - m), e1 = expf(l1 - m), e2 = expf(l2 - m), e3 = expf(l3 - m);
    float inv = 1.f / (e0 + e1 + e2 + e3);
    float attn[NPOINTS] = { e0 * inv, e1 * inv, e2 * inv, e3 * inv };

    const int ww = *wp;
    const int hh = *hp;
    const float rx = sref[bql * 2 + 0];
    const float ry = sref[bql * 2 + 1];
    const int vbase = b * HWTOT * DMODEL + h * DHEAD;

    const long tslot = (long)bq * NHEADS + h;
    int* ti = g_tidx + tslot * 16;
    float* tw = g_tw + tslot * 16;

    #pragma unroll
    for (int p = 0; p < NPOINTS; p++) {
        const int hp4 = h * NPOINTS + p;
        float lx = fminf(fmaxf(rx + pr[hp4 * 2 + 0], 0.f), 1.f);
        float ly = fminf(fmaxf(ry + pr[hp4 * 2 + 1], 0.f), 1.f);
        float sx = lx * (float)(ww - 1);
        float sy = ly * (float)(hh - 1);
        int x0 = (int)floorf(sx); x0 = min(max(x0, 0), ww - 1);
        int y0 = (int)floorf(sy); y0 = min(max(y0, 0), hh - 1);
        int x1 = min(x0 + 1, ww - 1);
        int y1 = min(y0 + 1, hh - 1);
        float wx1 = sx - (float)x0, wx0 = 1.f - wx1;
        float wy1 = sy - (float)y0, wy0 = 1.f - wy1;
        float a = attn[p];
        ti[p * 4 + 0] = vbase + (y0 * ww + x0) * DMODEL;
        ti[p * 4 + 1] = vbase + (y1 * ww + x0) * DMODEL;
        ti[p * 4 + 2] = vbase + (y0 * ww + x1) * DMODEL;
        ti[p * 4 + 3] = vbase + (y1 * ww + x1) * DMODEL;
        tw[p * 4 + 0] = wx0 * wy0 * a;
        tw[p * 4 + 1] = wx0 * wy1 * a;
        tw[p * 4 + 2] = wx1 * wy0 * a;
        tw[p * 4 + 3] = wx1 * wy1 * a;
    }
}

// ---------------------------------------------------------------------------
// Gather: warp handles TWO (bq, head) groups (32 loads in flight), lane = ch.
// ---------------------------------------------------------------------------
__global__ __launch_bounds__(256) void gather_kernel()
{
    const int wg0 = ((blockIdx.x * blockDim.x + threadIdx.x) >> 5) * 2;
    const int lane = threadIdx.x & 31;
    if (wg0 >= BATCH * QLEN * NHEADS) return;

    const int4* ti0 = (const int4*)(g_tidx + (long)wg0 * 16);
    const float4* tw0 = (const float4*)(g_tw + (long)wg0 * 16);
    const int4* ti1 = (const int4*)(g_tidx + (long)(wg0 + 1) * 16);
    const float4* tw1 = (const float4*)(g_tw + (long)(wg0 + 1) * 16);

    float acc0 = 0.f, acc1 = 0.f;
    #pragma unroll
    for (int c = 0; c < 4; c++) {
        int4 idA = ti0[c];
        int4 idB = ti1[c];
        float4 wA = tw0[c];
        float4 wB = tw1[c];
        acc0 = fmaf(wA.x, __half2float(g_valh[idA.x + lane]), acc0);
        acc1 = fmaf(wB.x, __half2float(g_valh[idB.x + lane]), acc1);
        acc0 = fmaf(wA.y, __half2float(g_valh[idA.y + lane]), acc0);
        acc1 = fmaf(wB.y, __half2float(g_valh[idB.y + lane]), acc1);
        acc0 = fmaf(wA.z, __half2float(g_valh[idA.z + lane]), acc0);
        acc1 = fmaf(wB.z, __half2float(g_valh[idB.z + lane]), acc1);
        acc0 = fmaf(wA.w, __half2float(g_valh[idA.w + lane]), acc0);
        acc1 = fmaf(wB.w, __half2float(g_valh[idB.w + lane]), acc1);
    }

    const int bq0 = wg0 >> 3, h0 = wg0 & 7;
    const int bq1 = (wg0 + 1) >> 3, h1 = (wg0 + 1) & 7;
    g_samph[(long)bq0 * DMODEL + h0 * DHEAD + lane] = __float2half_rn(acc0);
    g_samph[(long)bq1 * DMODEL + h1 * DHEAD + lane] = __float2half_rn(acc1);
}

// ---------------------------------------------------------------------------
// Launch — R16 topology:
//   s0: transpose(both), GEMM1, gather, GEMM4
//   s1: proj path (wcat, proj GEMM, prep_tab)
// ---------------------------------------------------------------------------
extern "C" void kernel_launch(void* const* d_in, const int* in_sizes, int n_in,
                              void* d_out, int out_size)
{
    const float* query   = (const float*)d_in[0];
    const float* ref_pts = (const float*)d_in[1];
    const float* inp     = (const float*)d_in[2];
    const int*   hp      = (const int*)d_in[3];
    const int*   wp      = (const int*)d_in[4];
    const float* W_off   = (const float*)d_in[5];
    const float* b_off   = (const float*)d_in[6];
    const float* W_attn  = (const float*)d_in[7];
    const float* b_attn  = (const float*)d_in[8];
    const float* W_val   = (const float*)d_in[9];
    const float* b_val   = (const float*)d_in[10];
    const float* W_out   = (const float*)d_in[11];
    const float* b_out   = (const float*)d_in[12];
    float* out = (float*)d_out;

    __half *valh_ptr, *samph_ptr, *wvth_ptr, *woth_ptr;
    float *proj_ptr, *wcat_ptr, *bcat_ptr;
    cudaGetSymbolAddress((void**)&valh_ptr, g_valh);
    cudaGetSymbolAddress((void**)&samph_ptr, g_samph);
    cudaGetSymbolAddress((void**)&proj_ptr, g_proj);
    cudaGetSymbolAddress((void**)&wcat_ptr, g_Wcat);
    cudaGetSymbolAddress((void**)&bcat_ptr, g_bcat);
    cudaGetSymbolAddress((void**)&wvth_ptr, g_WvalTh);
    cudaGetSymbolAddress((void**)&woth_ptr, g_WoutTh);

    static cudaStream_t s1 = nullptr;
    static cudaEvent_t evFork = nullptr, evJoin = nullptr;
    if (!s1) {
        cudaStreamCreateWithFlags(&s1, cudaStreamNonBlocking);
        cudaEventCreateWithFlags(&evFork, cudaEventDisableTiming);
        cudaEventCreateWithFlags(&evJoin, cudaEventDisableTiming);
        cudaFuncSetAttribute(tf32_split_gemm_kernel,
                             cudaFuncAttributeMaxDynamicSharedMemorySize, GEMM_SMEM_BYTES);
        cudaFuncSetAttribute((fp16_gemm_kernel<false, true>),
                             cudaFuncAttributeMaxDynamicSharedMemorySize, FP16_SMEM_F32A);
        cudaFuncSetAttribute((fp16_gemm_kernel<true, false>),
                             cudaFuncAttributeMaxDynamicSharedMemorySize, FP16_SMEM_H16A);
    }

    const int M1 = BATCH * HWTOT;   // 80000
    const int MQ = BATCH * QLEN;    // 16384

    // ---- fork: s1 runs the (independent) projection path
    cudaEventRecord(evFork, 0);
    cudaStreamWaitEvent(s1, evFork, 0);

    prep_wcat_kernel<<<(DMODEL * NPROJ + 255) / 256, 256, 0, s1>>>(
        W_off, b_off, W_attn, b_attn);
    {
        dim3 grid(1, MQ / GBM);
        tf32_split_gemm_kernel<<<grid, 256, GEMM_SMEM_BYTES, s1>>>(
            query, wcat_ptr, bcat_ptr, proj_ptr, MQ, NPROJ, DMODEL);
    }
    prep_tab_kernel<<<MQ / 32, 256, 0, s1>>>(ref_pts, hp, wp);
    cudaEventRecord(evJoin, s1);

    // ---- s0: both transposes in one launch, then the monolithic value GEMM
    transpose_both_kernel<<<128, dim3(32, 8)>>>(W_val, W_out);
    {
        dim3 grid(DMODEL / FBN, M1 / FBM);
        fp16_gemm_kernel<false, true><<<grid, 256, FP16_SMEM_F32A>>>(
            inp, wvth_ptr, b_val, valh_ptr, DMODEL, DMODEL);
    }

    // ---- join: gather needs values (s0) + table (s1)
    cudaStreamWaitEvent(0, evJoin, 0);
    gather_kernel<<<(MQ * NHEADS) / 16, 256>>>();

    // out = sampled(h) @ W_out + b_out   (pure half GEMM, fp32 out)
    {
        dim3 grid(DMODEL / FBN, MQ / FBM);
        fp16_gemm_kernel<true, false><<<grid, 256, FP16_SMEM_H16A>>>(
            samph_ptr, woth_ptr, b_out, out, DMODEL, DMODEL);
    }
}